// round 9
// baseline (speedup 1.0000x reference)
#include <cuda_runtime.h>
#include <cuda_bf16.h>
#include <math.h>

// ---------------------------------------------------------------------------
// Problem constants (fixed-shape instance)
// ---------------------------------------------------------------------------
#define B_    2
#define Q_    900
#define C_    256
#define NCAM  6
#define BQ    (B_ * Q_)          // 1800
#define BNQ   (B_ * NCAM * Q_)   // 10800

// levels: (H,W) = (112,200),(56,100),(28,50),(14,25)
// scale factors W/800 and H/448 are identical per level: .25 .125 .0625 .03125

// ---------------------------------------------------------------------------
// Scratch (device globals; no dynamic allocation allowed)
// ---------------------------------------------------------------------------
__device__ float g_maskf[BQ];
__device__ float g_keep[BQ];
__device__ float g_invext[B_ * NCAM * 16];
__device__ float g_pts[BNQ * 2];
__device__ int   g_inval[BNQ];
__device__ __align__(16) float g_ms[BNQ * C_];     // 11.06 MB
__device__ __align__(16) float g_q[BQ * C_];
__device__ __align__(16) float g_v[BNQ * C_];      // 11.06 MB
__device__ __align__(16) float g_fused[BQ * C_];

// ---------------------------------------------------------------------------
// Kernel 1: mask dtype detection + mask arrays + 4x4 extrinsic inverses
// ---------------------------------------------------------------------------
__global__ void prep_kernel(const void* __restrict__ mask_raw,
                            const float* __restrict__ ext)
{
    __shared__ int s_byte;
    if (threadIdx.x == 0) s_byte = 0;
    __syncthreads();

    // Detect mask element width. Scan first 450 words = 1800 bytes, safe for
    // uint8 (1800B), int32 (7200B) and float32 (7200B) interpretations.
    const unsigned int* w = (const unsigned int*)mask_raw;
    for (int i = threadIdx.x; i < 450; i += blockDim.x) {
        unsigned int x = w[i];
        if (x != 0u && x != 1u && x != 0x3F800000u) atomicOr(&s_byte, 1);
    }
    __syncthreads();
    const bool isbyte = (s_byte != 0);
    const unsigned char* bytes = (const unsigned char*)mask_raw;
    for (int i = threadIdx.x; i < BQ; i += blockDim.x) {
        bool mk = isbyte ? (bytes[i] != 0) : (w[i] != 0u);
        g_maskf[i] = mk ? 1.0f : 0.0f;
        g_keep[i]  = mk ? 0.0f : 1.0f;
    }

    // 4x4 inverses (Gauss-Jordan, partial pivoting, fp64) + nan_to_num
    int t = threadIdx.x;
    if (t < B_ * NCAM) {
        double a[4][8];
        for (int i = 0; i < 4; i++) {
            for (int j = 0; j < 4; j++) {
                a[i][j]     = (double)ext[t * 16 + i * 4 + j];
                a[i][4 + j] = (i == j) ? 1.0 : 0.0;
            }
        }
        for (int col = 0; col < 4; col++) {
            int piv = col; double best = fabs(a[col][col]);
            for (int r = col + 1; r < 4; r++) {
                double v = fabs(a[r][col]);
                if (v > best) { best = v; piv = r; }
            }
            if (piv != col) {
                for (int j = 0; j < 8; j++) { double tmp = a[col][j]; a[col][j] = a[piv][j]; a[piv][j] = tmp; }
            }
            double d = a[col][col];
            for (int j = 0; j < 8; j++) a[col][j] /= d;
            for (int r = 0; r < 4; r++) {
                if (r == col) continue;
                double f = a[r][col];
                for (int j = 0; j < 8; j++) a[r][j] -= f * a[col][j];
            }
        }
        for (int i = 0; i < 4; i++) {
            for (int j = 0; j < 4; j++) {
                float v = (float)a[i][4 + j];
                if (isnan(v)) v = 0.0f;
                else if (isinf(v)) v = (v > 0.0f) ? 1e6f : -1e6f;
                g_invext[t * 16 + i * 4 + j] = v;
            }
        }
    }
}

// ---------------------------------------------------------------------------
// Kernel 2: per (b,n,q) projection to image plane
// ---------------------------------------------------------------------------
__global__ void proj_kernel(const float* __restrict__ refp,
                            const float* __restrict__ intr)
{
    int p = blockIdx.x * blockDim.x + threadIdx.x;
    if (p >= BNQ) return;
    int bn = p / Q_;
    int qq = p % Q_;
    int b  = bn / NCAM;

    float rx, ry, rz;
    if (g_maskf[b * Q_ + qq] != 0.0f) {
        rx = ry = rz = -1000.0f;
    } else {
        const float* rp = refp + (b * Q_ + qq) * 3;
        rx = rp[0] * 102.4f - 51.2f;
        ry = rp[1] * 102.4f - 51.2f;
        rz = rp[2] * 102.4f - 51.2f;
    }

    const float* M = g_invext + bn * 16;
    float pch[4];
#pragma unroll
    for (int i = 0; i < 4; i++)
        pch[i] = M[i*4+0]*rx + M[i*4+1]*ry + M[i*4+2]*rz + M[i*4+3];

    float d = pch[2];
    if (isnan(d)) d = 10.0f;
    else if (isinf(d)) d = (d > 0.0f) ? 100.0f : -100.0f;
    int invd = d < 1.5f;
    float ds = fmaxf(d, 1.5f);
    float pc0 = pch[0] / ds, pc1 = pch[1] / ds, pc2 = pch[2] / ds;

    const float* K = intr + bn * 9;
    float ix = K[0]*pc0 + K[1]*pc1 + K[2]*pc2;
    float iy = K[3]*pc0 + K[4]*pc1 + K[5]*pc2;
    ix = fminf(fmaxf(ix, -3000.0f), 3000.0f);
    iy = fminf(fmaxf(iy, -3000.0f), 3000.0f);
    g_pts[p * 2 + 0] = ix;
    g_pts[p * 2 + 1] = iy;
    g_inval[p] = invd;
}

// ---------------------------------------------------------------------------
// Kernel 3: bilinear sampling, 4 levels, accumulate into ms[b,n,q,c]
// one block per (b,n,q), 256 threads = channels
// ---------------------------------------------------------------------------
__global__ void sample_kernel(const float* __restrict__ f0,
                              const float* __restrict__ f1,
                              const float* __restrict__ f2,
                              const float* __restrict__ f3)
{
    const int p  = blockIdx.x;       // (b*N+n)*Q + q
    const int bn = p / Q_;

    __shared__ int   sidx[16];
    __shared__ float sw[16];

    const int tid = threadIdx.x;
    if (tid < 4) {
        const int l = tid;
        const int WFs[4] = {200, 100, 50, 25};
        const int HFs[4] = {112, 56, 28, 14};
        const float scl[4] = {0.25f, 0.125f, 0.0625f, 0.03125f};
        const int Wf = WFs[l], Hf = HFs[l];
        float gx, gy;
        if (g_inval[p]) {
            gx = -100.0f; gy = -100.0f;
        } else {
            float fx = g_pts[2 * p + 0] * scl[l];
            float fy = g_pts[2 * p + 1] * scl[l];
            gx = fx / (float)(Wf - 1) * 2.0f - 1.0f;
            gy = fy / (float)(Hf - 1) * 2.0f - 1.0f;
            gx = fminf(fmaxf(gx, -10.0f), 10.0f);
            gy = fminf(fmaxf(gy, -10.0f), 10.0f);
        }
        float px = (gx + 1.0f) * 0.5f * (float)(Wf - 1);
        float py = (gy + 1.0f) * 0.5f * (float)(Hf - 1);
        float x0f = floorf(px), y0f = floorf(py);
        int x0 = (int)x0f, y0 = (int)y0f;
        float wx1 = px - x0f, wy1 = py - y0f;
        float wx0 = 1.0f - wx1, wy0 = 1.0f - wy1;

        int   cx[4] = {x0, x0 + 1, x0, x0 + 1};
        int   cy[4] = {y0, y0, y0 + 1, y0 + 1};
        float cw[4] = {wx0 * wy0, wx1 * wy0, wx0 * wy1, wx1 * wy1};
#pragma unroll
        for (int k = 0; k < 4; k++) {
            int xi = cx[k], yi = cy[k];
            bool valid = (xi >= 0) && (xi < Wf) && (yi >= 0) && (yi < Hf);
            int xc = min(max(xi, 0), Wf - 1);
            int yc = min(max(yi, 0), Hf - 1);
            sidx[l * 4 + k] = yc * Wf + xc;
            sw[l * 4 + k]   = valid ? cw[k] : 0.0f;
        }
    }
    __syncthreads();

    const int c = tid;
    const float* base0 = f0 + (size_t)(bn * C_ + c) * 22400;
    const float* base1 = f1 + (size_t)(bn * C_ + c) * 5600;
    const float* base2 = f2 + (size_t)(bn * C_ + c) * 1400;
    const float* base3 = f3 + (size_t)(bn * C_ + c) * 350;
    const float* bases[4] = {base0, base1, base2, base3};

    float sum = 0.0f;
#pragma unroll
    for (int l = 0; l < 4; l++) {
#pragma unroll
        for (int k = 0; k < 4; k++) {
            float w = sw[l * 4 + k];
            if (w != 0.0f) sum += w * __ldg(&bases[l][sidx[l * 4 + k]]);
        }
    }
    g_ms[(size_t)p * C_ + c] = 0.25f * sum;
}

// ---------------------------------------------------------------------------
// SGEMM: out[m, j] = (sum_k A[m,k] * W[j,k] + bias[j]) * keep[m]
// A row-major [M,256], W row-major [256,256]. 128x128 tile, TK=8, 8x8 micro.
// ---------------------------------------------------------------------------
__global__ __launch_bounds__(256) void sgemm_nt(const float* __restrict__ A,
                                                const float* __restrict__ W,
                                                const float* __restrict__ bias,
                                                const float* __restrict__ keep,
                                                float* __restrict__ out, int M)
{
    __shared__ float As[8][128];
    __shared__ float Bs[8][128];

    const int tid  = threadIdx.x;
    const int row0 = blockIdx.y * 128;
    const int col0 = blockIdx.x * 128;

    const int lr = tid >> 1;          // 0..127
    const int lk = (tid & 1) * 4;     // 0 or 4
    const int tx = tid & 15;          // 0..15
    const int ty = tid >> 4;          // 0..15

    float acc[8][8];
#pragma unroll
    for (int i = 0; i < 8; i++)
#pragma unroll
        for (int j = 0; j < 8; j++) acc[i][j] = 0.0f;

    for (int k0 = 0; k0 < 256; k0 += 8) {
        {
            int gr = row0 + lr;
            float4 v = (gr < M) ? *(const float4*)(A + (size_t)gr * 256 + k0 + lk)
                                : make_float4(0.f, 0.f, 0.f, 0.f);
            As[lk + 0][lr] = v.x; As[lk + 1][lr] = v.y;
            As[lk + 2][lr] = v.z; As[lk + 3][lr] = v.w;
        }
        {
            int gc = col0 + lr;   // always < 256
            float4 v = *(const float4*)(W + (size_t)gc * 256 + k0 + lk);
            Bs[lk + 0][lr] = v.x; Bs[lk + 1][lr] = v.y;
            Bs[lk + 2][lr] = v.z; Bs[lk + 3][lr] = v.w;
        }
        __syncthreads();
#pragma unroll
        for (int kk = 0; kk < 8; kk++) {
            float a[8], b[8];
#pragma unroll
            for (int i = 0; i < 8; i++) a[i] = As[kk][ty * 8 + i];
#pragma unroll
            for (int j = 0; j < 8; j++) b[j] = Bs[kk][tx * 8 + j];
#pragma unroll
            for (int i = 0; i < 8; i++)
#pragma unroll
                for (int j = 0; j < 8; j++) acc[i][j] += a[i] * b[j];
        }
        __syncthreads();
    }

#pragma unroll
    for (int i = 0; i < 8; i++) {
        int gr = row0 + ty * 8 + i;
        if (gr >= M) continue;
        float ks = keep ? keep[gr] : 1.0f;
#pragma unroll
        for (int j = 0; j < 8; j++) {
            int gc = col0 + tx * 8 + j;
            out[(size_t)gr * 256 + gc] = (acc[i][j] + bias[gc]) * ks;
        }
    }
}

// ---------------------------------------------------------------------------
// Kernel: max over cameras + fused = relu(q + max) + q
// ---------------------------------------------------------------------------
__global__ void maxfuse_kernel()
{
    int idx = blockIdx.x * blockDim.x + threadIdx.x;
    if (idx >= BQ * C_) return;
    int m = idx >> 8;           // b*Q + q
    int c = idx & 255;
    int b = m / Q_, qq = m % Q_;
    float mx = -INFINITY;
#pragma unroll
    for (int n = 0; n < NCAM; n++) {
        mx = fmaxf(mx, g_v[((size_t)(b * NCAM + n) * Q_ + qq) * C_ + c]);
    }
    float qv = g_q[idx];
    float f = fmaxf(qv + mx, 0.0f);
    g_fused[idx] = f + qv;
}

// ---------------------------------------------------------------------------
// Launch
// ---------------------------------------------------------------------------
extern "C" void kernel_launch(void* const* d_in, const int* in_sizes, int n_in,
                              void* d_out, int out_size)
{
    const float* query = (const float*)d_in[0];
    const float* refp  = (const float*)d_in[1];
    const void*  mask  = d_in[2];
    const float* intr  = (const float*)d_in[3];
    const float* ext   = (const float*)d_in[4];
    const float* f0    = (const float*)d_in[5];
    const float* f1    = (const float*)d_in[6];
    const float* f2    = (const float*)d_in[7];
    const float* f3    = (const float*)d_in[8];
    const float* Wq    = (const float*)d_in[9];
    const float* bq    = (const float*)d_in[10];
    const float* Wv    = (const float*)d_in[11];
    const float* bv    = (const float*)d_in[12];
    const float* Wo    = (const float*)d_in[13];
    const float* bo    = (const float*)d_in[14];
    float* out = (float*)d_out;

    float *p_ms, *p_q, *p_v, *p_fused, *p_keep;
    cudaGetSymbolAddress((void**)&p_ms,    g_ms);
    cudaGetSymbolAddress((void**)&p_q,     g_q);
    cudaGetSymbolAddress((void**)&p_v,     g_v);
    cudaGetSymbolAddress((void**)&p_fused, g_fused);
    cudaGetSymbolAddress((void**)&p_keep,  g_keep);

    prep_kernel<<<1, 256>>>(mask, ext);
    proj_kernel<<<(BNQ + 255) / 256, 256>>>(refp, intr);
    sample_kernel<<<BNQ, 256>>>(f0, f1, f2, f3);

    // q = query @ Wq^T + bq
    sgemm_nt<<<dim3(2, (BQ + 127) / 128), 256>>>(query, Wq, bq, nullptr, p_q, BQ);
    // v = ms @ Wv^T + bv
    sgemm_nt<<<dim3(2, (BNQ + 127) / 128), 256>>>(p_ms, Wv, bv, nullptr, p_v, BNQ);
    // sampled = max_n v ; fused = relu(q + sampled) + q
    maxfuse_kernel<<<(BQ * C_ + 255) / 256, 256>>>();
    // out = (fused @ Wo^T + bo) * keep
    sgemm_nt<<<dim3(2, (BQ + 127) / 128), 256>>>(p_fused, Wo, bo, p_keep, out, BQ);
}

// round 11
// speedup vs baseline: 1.5013x; 1.5013x over previous
#include <cuda_runtime.h>
#include <cuda_bf16.h>
#include <math.h>

// ---------------------------------------------------------------------------
// Problem constants (fixed-shape instance)
// ---------------------------------------------------------------------------
#define B_    2
#define Q_    900
#define C_    256
#define NCAM  6
#define BQ    (B_ * Q_)          // 1800
#define BNQ   (B_ * NCAM * Q_)   // 10800

// ---------------------------------------------------------------------------
// Scratch (device globals; no dynamic allocation allowed)
// ---------------------------------------------------------------------------
__device__ float g_maskf[BQ];
__device__ float g_keep[BQ];
__device__ float g_invext[B_ * NCAM * 16];
__device__ float g_pts[BNQ * 2];
__device__ int   g_inval[BNQ];
__device__ __align__(16) float g_ms[BNQ * C_];     // 11.06 MB
__device__ __align__(16) float g_q[BQ * C_];
__device__ __align__(16) float g_v[BNQ * C_];      // 11.06 MB
__device__ __align__(16) float g_fused[BQ * C_];

// ---------------------------------------------------------------------------
// Kernel 1: mask dtype detection + mask arrays + 4x4 extrinsic inverses
// ---------------------------------------------------------------------------
__global__ void prep_kernel(const void* __restrict__ mask_raw,
                            const float* __restrict__ ext)
{
    __shared__ int s_byte;
    if (threadIdx.x == 0) s_byte = 0;
    __syncthreads();

    const unsigned int* w = (const unsigned int*)mask_raw;
    for (int i = threadIdx.x; i < 450; i += blockDim.x) {
        unsigned int x = w[i];
        if (x != 0u && x != 1u && x != 0x3F800000u) atomicOr(&s_byte, 1);
    }
    __syncthreads();
    const bool isbyte = (s_byte != 0);
    const unsigned char* bytes = (const unsigned char*)mask_raw;
    for (int i = threadIdx.x; i < BQ; i += blockDim.x) {
        bool mk = isbyte ? (bytes[i] != 0) : (w[i] != 0u);
        g_maskf[i] = mk ? 1.0f : 0.0f;
        g_keep[i]  = mk ? 0.0f : 1.0f;
    }

    int t = threadIdx.x;
    if (t < B_ * NCAM) {
        double a[4][8];
        for (int i = 0; i < 4; i++) {
            for (int j = 0; j < 4; j++) {
                a[i][j]     = (double)ext[t * 16 + i * 4 + j];
                a[i][4 + j] = (i == j) ? 1.0 : 0.0;
            }
        }
        for (int col = 0; col < 4; col++) {
            int piv = col; double best = fabs(a[col][col]);
            for (int r = col + 1; r < 4; r++) {
                double v = fabs(a[r][col]);
                if (v > best) { best = v; piv = r; }
            }
            if (piv != col) {
                for (int j = 0; j < 8; j++) { double tmp = a[col][j]; a[col][j] = a[piv][j]; a[piv][j] = tmp; }
            }
            double d = a[col][col];
            for (int j = 0; j < 8; j++) a[col][j] /= d;
            for (int r = 0; r < 4; r++) {
                if (r == col) continue;
                double f = a[r][col];
                for (int j = 0; j < 8; j++) a[r][j] -= f * a[col][j];
            }
        }
        for (int i = 0; i < 4; i++) {
            for (int j = 0; j < 4; j++) {
                float v = (float)a[i][4 + j];
                if (isnan(v)) v = 0.0f;
                else if (isinf(v)) v = (v > 0.0f) ? 1e6f : -1e6f;
                g_invext[t * 16 + i * 4 + j] = v;
            }
        }
    }
}

// ---------------------------------------------------------------------------
// Kernel 2: per (b,n,q) projection to image plane
// ---------------------------------------------------------------------------
__global__ void proj_kernel(const float* __restrict__ refp,
                            const float* __restrict__ intr)
{
    int p = blockIdx.x * blockDim.x + threadIdx.x;
    if (p >= BNQ) return;
    int bn = p / Q_;
    int qq = p % Q_;
    int b  = bn / NCAM;

    float rx, ry, rz;
    if (g_maskf[b * Q_ + qq] != 0.0f) {
        rx = ry = rz = -1000.0f;
    } else {
        const float* rp = refp + (b * Q_ + qq) * 3;
        rx = rp[0] * 102.4f - 51.2f;
        ry = rp[1] * 102.4f - 51.2f;
        rz = rp[2] * 102.4f - 51.2f;
    }

    const float* M = g_invext + bn * 16;
    float pch[4];
#pragma unroll
    for (int i = 0; i < 4; i++)
        pch[i] = M[i*4+0]*rx + M[i*4+1]*ry + M[i*4+2]*rz + M[i*4+3];

    float d = pch[2];
    if (isnan(d)) d = 10.0f;
    else if (isinf(d)) d = (d > 0.0f) ? 100.0f : -100.0f;
    int invd = d < 1.5f;
    float ds = fmaxf(d, 1.5f);
    float pc0 = pch[0] / ds, pc1 = pch[1] / ds, pc2 = pch[2] / ds;

    const float* K = intr + bn * 9;
    float ix = K[0]*pc0 + K[1]*pc1 + K[2]*pc2;
    float iy = K[3]*pc0 + K[4]*pc1 + K[5]*pc2;
    ix = fminf(fmaxf(ix, -3000.0f), 3000.0f);
    iy = fminf(fmaxf(iy, -3000.0f), 3000.0f);
    g_pts[p * 2 + 0] = ix;
    g_pts[p * 2 + 1] = iy;
    g_inval[p] = invd;
}

// ---------------------------------------------------------------------------
// Kernel 3: bilinear sampling, 4 levels, accumulate into ms[b,n,q,c]
// ---------------------------------------------------------------------------
__global__ void sample_kernel(const float* __restrict__ f0,
                              const float* __restrict__ f1,
                              const float* __restrict__ f2,
                              const float* __restrict__ f3)
{
    const int p  = blockIdx.x;       // (b*N+n)*Q + q
    const int bn = p / Q_;

    __shared__ int   sidx[16];
    __shared__ float sw[16];

    const int tid = threadIdx.x;
    if (tid < 4) {
        const int l = tid;
        const int WFs[4] = {200, 100, 50, 25};
        const int HFs[4] = {112, 56, 28, 14};
        const float scl[4] = {0.25f, 0.125f, 0.0625f, 0.03125f};
        const int Wf = WFs[l], Hf = HFs[l];
        float gx, gy;
        if (g_inval[p]) {
            gx = -100.0f; gy = -100.0f;
        } else {
            float fx = g_pts[2 * p + 0] * scl[l];
            float fy = g_pts[2 * p + 1] * scl[l];
            gx = fx / (float)(Wf - 1) * 2.0f - 1.0f;
            gy = fy / (float)(Hf - 1) * 2.0f - 1.0f;
            gx = fminf(fmaxf(gx, -10.0f), 10.0f);
            gy = fminf(fmaxf(gy, -10.0f), 10.0f);
        }
        float px = (gx + 1.0f) * 0.5f * (float)(Wf - 1);
        float py = (gy + 1.0f) * 0.5f * (float)(Hf - 1);
        float x0f = floorf(px), y0f = floorf(py);
        int x0 = (int)x0f, y0 = (int)y0f;
        float wx1 = px - x0f, wy1 = py - y0f;
        float wx0 = 1.0f - wx1, wy0 = 1.0f - wy1;

        int   cx[4] = {x0, x0 + 1, x0, x0 + 1};
        int   cy[4] = {y0, y0, y0 + 1, y0 + 1};
        float cw[4] = {wx0 * wy0, wx1 * wy0, wx0 * wy1, wx1 * wy1};
#pragma unroll
        for (int k = 0; k < 4; k++) {
            int xi = cx[k], yi = cy[k];
            bool valid = (xi >= 0) && (xi < Wf) && (yi >= 0) && (yi < Hf);
            int xc = min(max(xi, 0), Wf - 1);
            int yc = min(max(yi, 0), Hf - 1);
            sidx[l * 4 + k] = yc * Wf + xc;
            sw[l * 4 + k]   = valid ? cw[k] : 0.0f;
        }
    }
    __syncthreads();

    const int c = tid;
    const float* base0 = f0 + (size_t)(bn * C_ + c) * 22400;
    const float* base1 = f1 + (size_t)(bn * C_ + c) * 5600;
    const float* base2 = f2 + (size_t)(bn * C_ + c) * 1400;
    const float* base3 = f3 + (size_t)(bn * C_ + c) * 350;
    const float* bases[4] = {base0, base1, base2, base3};

    float sum = 0.0f;
#pragma unroll
    for (int l = 0; l < 4; l++) {
#pragma unroll
        for (int k = 0; k < 4; k++) {
            float w = sw[l * 4 + k];
            if (w != 0.0f) sum += w * __ldg(&bases[l][sidx[l * 4 + k]]);
        }
    }
    g_ms[(size_t)p * C_ + c] = 0.25f * sum;
}

// ---------------------------------------------------------------------------
// SGEMM 64x64 tile, TK=16, 4x4 micro, double-buffered. For M=1800 GEMMs.
// out[m, j] = (sum_k A[m,k] * W[j,k] + bias[j]) * keep[m]
// grid (4, ceil(M/64)), 256 threads.
// ---------------------------------------------------------------------------
__global__ __launch_bounds__(256) void sgemm64(const float* __restrict__ A,
                                               const float* __restrict__ W,
                                               const float* __restrict__ bias,
                                               const float* __restrict__ keep,
                                               float* __restrict__ out, int M)
{
    // pad rows to 68 floats: 272B row stride (16B aligned), store conflicts 2-way max
    __shared__ float As[2][16][68];
    __shared__ float Bs[2][16][68];

    const int tid  = threadIdx.x;
    const int row0 = blockIdx.y * 64;
    const int col0 = blockIdx.x * 64;

    const int tx = tid & 15;          // 0..15  -> cols tx*4..+3
    const int ty = tid >> 4;          // 0..15  -> rows ty*4..+3
    const int lr = tid >> 2;          // 0..63
    const int lk = (tid & 3) * 4;     // 0,4,8,12

    const int gr = row0 + lr;
    const float* Aptr = A + (size_t)gr * 256 + lk;
    const float* Wptr = W + (size_t)(col0 + lr) * 256 + lk;

    float acc[4][4];
#pragma unroll
    for (int i = 0; i < 4; i++)
#pragma unroll
        for (int j = 0; j < 4; j++) acc[i][j] = 0.0f;

    float4 av = (gr < M) ? *(const float4*)(Aptr) : make_float4(0.f,0.f,0.f,0.f);
    float4 bv = *(const float4*)(Wptr);
    As[0][lk+0][lr]=av.x; As[0][lk+1][lr]=av.y; As[0][lk+2][lr]=av.z; As[0][lk+3][lr]=av.w;
    Bs[0][lk+0][lr]=bv.x; Bs[0][lk+1][lr]=bv.y; Bs[0][lk+2][lr]=bv.z; Bs[0][lk+3][lr]=bv.w;
    __syncthreads();

#pragma unroll 1
    for (int t = 0; t < 16; t++) {
        const int buf = t & 1;
        if (t < 15) {
            const int k0 = (t + 1) * 16;
            av = (gr < M) ? *(const float4*)(Aptr + k0) : make_float4(0.f,0.f,0.f,0.f);
            bv = *(const float4*)(Wptr + k0);
        }
#pragma unroll
        for (int kk = 0; kk < 16; kk++) {
            float a[4], b[4];
            *(float4*)a = *(const float4*)&As[buf][kk][ty * 4];
            *(float4*)b = *(const float4*)&Bs[buf][kk][tx * 4];
#pragma unroll
            for (int i = 0; i < 4; i++)
#pragma unroll
                for (int j = 0; j < 4; j++) acc[i][j] += a[i] * b[j];
        }
        if (t < 15) {
            const int nb = buf ^ 1;
            As[nb][lk+0][lr]=av.x; As[nb][lk+1][lr]=av.y; As[nb][lk+2][lr]=av.z; As[nb][lk+3][lr]=av.w;
            Bs[nb][lk+0][lr]=bv.x; Bs[nb][lk+1][lr]=bv.y; Bs[nb][lk+2][lr]=bv.z; Bs[nb][lk+3][lr]=bv.w;
        }
        __syncthreads();
    }

    const float4 bias4 = *(const float4*)(bias + col0 + tx * 4);
#pragma unroll
    for (int i = 0; i < 4; i++) {
        int r = row0 + ty * 4 + i;
        if (r >= M) continue;
        float ks = keep ? keep[r] : 1.0f;
        float4 o;
        o.x = (acc[i][0] + bias4.x) * ks;
        o.y = (acc[i][1] + bias4.y) * ks;
        o.z = (acc[i][2] + bias4.z) * ks;
        o.w = (acc[i][3] + bias4.w) * ks;
        *(float4*)(out + (size_t)r * 256 + col0 + tx * 4) = o;
    }
}

// ---------------------------------------------------------------------------
// SGEMM 128x128 tile, TK=8, 8x8 micro, double-buffered. For the M=10800 GEMM.
// grid (2, ceil(M/128)), 256 threads.
// ---------------------------------------------------------------------------
__global__ __launch_bounds__(256) void sgemm128(const float* __restrict__ A,
                                                const float* __restrict__ W,
                                                const float* __restrict__ bias,
                                                float* __restrict__ out, int M)
{
    // pad rows to 132 floats: 528B stride (16B aligned), conflict-free stores
    __shared__ float As[2][8][132];
    __shared__ float Bs[2][8][132];

    const int tid  = threadIdx.x;
    const int row0 = blockIdx.y * 128;
    const int col0 = blockIdx.x * 128;

    const int tx = tid & 15;          // cols tx*8..+7
    const int ty = tid >> 4;          // rows ty*8..+7
    const int lr = tid >> 1;          // 0..127
    const int lk = (tid & 1) * 4;     // 0 or 4

    const int gr = row0 + lr;
    const float* Aptr = A + (size_t)gr * 256 + lk;
    const float* Wptr = W + (size_t)(col0 + lr) * 256 + lk;

    float acc[8][8];
#pragma unroll
    for (int i = 0; i < 8; i++)
#pragma unroll
        for (int j = 0; j < 8; j++) acc[i][j] = 0.0f;

    float4 av = (gr < M) ? *(const float4*)(Aptr) : make_float4(0.f,0.f,0.f,0.f);
    float4 bv = *(const float4*)(Wptr);
    As[0][lk+0][lr]=av.x; As[0][lk+1][lr]=av.y; As[0][lk+2][lr]=av.z; As[0][lk+3][lr]=av.w;
    Bs[0][lk+0][lr]=bv.x; Bs[0][lk+1][lr]=bv.y; Bs[0][lk+2][lr]=bv.z; Bs[0][lk+3][lr]=bv.w;
    __syncthreads();

#pragma unroll 1
    for (int t = 0; t < 32; t++) {
        const int buf = t & 1;
        if (t < 31) {
            const int k0 = (t + 1) * 8;
            av = (gr < M) ? *(const float4*)(Aptr + k0) : make_float4(0.f,0.f,0.f,0.f);
            bv = *(const float4*)(Wptr + k0);
        }
#pragma unroll
        for (int kk = 0; kk < 8; kk++) {
            float a[8], b[8];
            *(float4*)&a[0] = *(const float4*)&As[buf][kk][ty * 8 + 0];
            *(float4*)&a[4] = *(const float4*)&As[buf][kk][ty * 8 + 4];
            *(float4*)&b[0] = *(const float4*)&Bs[buf][kk][tx * 8 + 0];
            *(float4*)&b[4] = *(const float4*)&Bs[buf][kk][tx * 8 + 4];
#pragma unroll
            for (int i = 0; i < 8; i++)
#pragma unroll
                for (int j = 0; j < 8; j++) acc[i][j] += a[i] * b[j];
        }
        if (t < 31) {
            const int nb = buf ^ 1;
            As[nb][lk+0][lr]=av.x; As[nb][lk+1][lr]=av.y; As[nb][lk+2][lr]=av.z; As[nb][lk+3][lr]=av.w;
            Bs[nb][lk+0][lr]=bv.x; Bs[nb][lk+1][lr]=bv.y; Bs[nb][lk+2][lr]=bv.z; Bs[nb][lk+3][lr]=bv.w;
        }
        __syncthreads();
    }

    const float4 bias4lo = *(const float4*)(bias + col0 + tx * 8 + 0);
    const float4 bias4hi = *(const float4*)(bias + col0 + tx * 8 + 4);
#pragma unroll
    for (int i = 0; i < 8; i++) {
        int r = row0 + ty * 8 + i;
        if (r >= M) continue;
        float4 o0, o1;
        o0.x = acc[i][0] + bias4lo.x; o0.y = acc[i][1] + bias4lo.y;
        o0.z = acc[i][2] + bias4lo.z; o0.w = acc[i][3] + bias4lo.w;
        o1.x = acc[i][4] + bias4hi.x; o1.y = acc[i][5] + bias4hi.y;
        o1.z = acc[i][6] + bias4hi.z; o1.w = acc[i][7] + bias4hi.w;
        *(float4*)(out + (size_t)r * 256 + col0 + tx * 8 + 0) = o0;
        *(float4*)(out + (size_t)r * 256 + col0 + tx * 8 + 4) = o1;
    }
}

// ---------------------------------------------------------------------------
// Kernel: max over cameras + fused = relu(q + max) + q  (float4-vectorized)
// ---------------------------------------------------------------------------
__global__ void maxfuse_kernel()
{
    int idx = blockIdx.x * blockDim.x + threadIdx.x;   // over BQ * C/4
    if (idx >= BQ * (C_ / 4)) return;
    int m = idx / (C_ / 4);        // b*Q + q
    int c4 = idx % (C_ / 4);
    int b = m / Q_, qq = m % Q_;

    float4 mx = make_float4(-INFINITY, -INFINITY, -INFINITY, -INFINITY);
#pragma unroll
    for (int n = 0; n < NCAM; n++) {
        const float4 v = *(const float4*)&g_v[(((size_t)(b * NCAM + n) * Q_ + qq) * C_) + c4 * 4];
        mx.x = fmaxf(mx.x, v.x); mx.y = fmaxf(mx.y, v.y);
        mx.z = fmaxf(mx.z, v.z); mx.w = fmaxf(mx.w, v.w);
    }
    const float4 qv = *(const float4*)&g_q[(size_t)m * C_ + c4 * 4];
    float4 f;
    f.x = fmaxf(qv.x + mx.x, 0.0f) + qv.x;
    f.y = fmaxf(qv.y + mx.y, 0.0f) + qv.y;
    f.z = fmaxf(qv.z + mx.z, 0.0f) + qv.z;
    f.w = fmaxf(qv.w + mx.w, 0.0f) + qv.w;
    *(float4*)&g_fused[(size_t)m * C_ + c4 * 4] = f;
}

// ---------------------------------------------------------------------------
// Launch
// ---------------------------------------------------------------------------
extern "C" void kernel_launch(void* const* d_in, const int* in_sizes, int n_in,
                              void* d_out, int out_size)
{
    const float* query = (const float*)d_in[0];
    const float* refp  = (const float*)d_in[1];
    const void*  mask  = d_in[2];
    const float* intr  = (const float*)d_in[3];
    const float* ext   = (const float*)d_in[4];
    const float* f0    = (const float*)d_in[5];
    const float* f1    = (const float*)d_in[6];
    const float* f2    = (const float*)d_in[7];
    const float* f3    = (const float*)d_in[8];
    const float* Wq    = (const float*)d_in[9];
    const float* bq    = (const float*)d_in[10];
    const float* Wv    = (const float*)d_in[11];
    const float* bv    = (const float*)d_in[12];
    const float* Wo    = (const float*)d_in[13];
    const float* bo    = (const float*)d_in[14];
    float* out = (float*)d_out;

    float *p_ms, *p_q, *p_v, *p_fused, *p_keep;
    cudaGetSymbolAddress((void**)&p_ms,    g_ms);
    cudaGetSymbolAddress((void**)&p_q,     g_q);
    cudaGetSymbolAddress((void**)&p_v,     g_v);
    cudaGetSymbolAddress((void**)&p_fused, g_fused);
    cudaGetSymbolAddress((void**)&p_keep,  g_keep);

    prep_kernel<<<1, 256>>>(mask, ext);
    proj_kernel<<<(BNQ + 255) / 256, 256>>>(refp, intr);
    sample_kernel<<<BNQ, 256>>>(f0, f1, f2, f3);

    // q = query @ Wq^T + bq            (116 blocks)
    sgemm64<<<dim3(4, (BQ + 63) / 64), 256>>>(query, Wq, bq, nullptr, p_q, BQ);
    // v = ms @ Wv^T + bv               (170 blocks)
    sgemm128<<<dim3(2, (BNQ + 127) / 128), 256>>>(p_ms, Wv, bv, p_v, BNQ);
    // sampled = max_n v ; fused = relu(q + sampled) + q
    maxfuse_kernel<<<(BQ * (C_ / 4) + 255) / 256, 256>>>();
    // out = (fused @ Wo^T + bo) * keep (116 blocks)
    sgemm64<<<dim3(4, (BQ + 63) / 64), 256>>>(p_fused, Wo, bo, p_keep, out, BQ);
}

// round 12
// speedup vs baseline: 1.6997x; 1.1322x over previous
#include <cuda_runtime.h>
#include <cuda_bf16.h>
#include <math.h>

// ---------------------------------------------------------------------------
// Problem constants (fixed-shape instance)
// ---------------------------------------------------------------------------
#define B_    2
#define Q_    900
#define C_    256
#define NCAM  6
#define BQ    (B_ * Q_)          // 1800
#define BNQ   (B_ * NCAM * Q_)   // 10800

// ---------------------------------------------------------------------------
// Scratch (device globals; no dynamic allocation allowed)
// ---------------------------------------------------------------------------
__device__ float g_maskf[BQ];
__device__ float g_keep[BQ];
__device__ float g_invext[B_ * NCAM * 16];
__device__ __align__(16) float g_ms[BNQ * C_];     // 11.06 MB
__device__ __align__(16) float g_q[BQ * C_];
__device__ __align__(16) float g_v[BNQ * C_];      // 11.06 MB
__device__ __align__(16) float g_fused[BQ * C_];

// ---------------------------------------------------------------------------
// Kernel 1: mask dtype detection + mask arrays + 4x4 extrinsic inverses
// ---------------------------------------------------------------------------
__global__ void prep_kernel(const void* __restrict__ mask_raw,
                            const float* __restrict__ ext)
{
    __shared__ int s_byte;
    if (threadIdx.x == 0) s_byte = 0;
    __syncthreads();

    const unsigned int* w = (const unsigned int*)mask_raw;
    for (int i = threadIdx.x; i < 450; i += blockDim.x) {
        unsigned int x = w[i];
        if (x != 0u && x != 1u && x != 0x3F800000u) atomicOr(&s_byte, 1);
    }
    __syncthreads();
    const bool isbyte = (s_byte != 0);
    const unsigned char* bytes = (const unsigned char*)mask_raw;
    for (int i = threadIdx.x; i < BQ; i += blockDim.x) {
        bool mk = isbyte ? (bytes[i] != 0) : (w[i] != 0u);
        g_maskf[i] = mk ? 1.0f : 0.0f;
        g_keep[i]  = mk ? 0.0f : 1.0f;
    }

    int t = threadIdx.x;
    if (t < B_ * NCAM) {
        double a[4][8];
        for (int i = 0; i < 4; i++) {
            for (int j = 0; j < 4; j++) {
                a[i][j]     = (double)ext[t * 16 + i * 4 + j];
                a[i][4 + j] = (i == j) ? 1.0 : 0.0;
            }
        }
        for (int col = 0; col < 4; col++) {
            int piv = col; double best = fabs(a[col][col]);
            for (int r = col + 1; r < 4; r++) {
                double v = fabs(a[r][col]);
                if (v > best) { best = v; piv = r; }
            }
            if (piv != col) {
                for (int j = 0; j < 8; j++) { double tmp = a[col][j]; a[col][j] = a[piv][j]; a[piv][j] = tmp; }
            }
            double d = a[col][col];
            for (int j = 0; j < 8; j++) a[col][j] /= d;
            for (int r = 0; r < 4; r++) {
                if (r == col) continue;
                double f = a[r][col];
                for (int j = 0; j < 8; j++) a[r][j] -= f * a[col][j];
            }
        }
        for (int i = 0; i < 4; i++) {
            for (int j = 0; j < 4; j++) {
                float v = (float)a[i][4 + j];
                if (isnan(v)) v = 0.0f;
                else if (isinf(v)) v = (v > 0.0f) ? 1e6f : -1e6f;
                g_invext[t * 16 + i * 4 + j] = v;
            }
        }
    }
}

// ---------------------------------------------------------------------------
// Kernel 2: projection + bilinear sampling (fused), 4 levels
// one block per (b,n,q); threads 0..3 each redo the tiny projection and
// derive their level's corner indices/weights; 256 threads gather channels.
// ---------------------------------------------------------------------------
__global__ void sample_kernel(const float* __restrict__ refp,
                              const float* __restrict__ intr,
                              const float* __restrict__ f0,
                              const float* __restrict__ f1,
                              const float* __restrict__ f2,
                              const float* __restrict__ f3)
{
    const int p  = blockIdx.x;       // (b*N+n)*Q + q
    const int bn = p / Q_;
    const int qq = p % Q_;
    const int b  = bn / NCAM;

    __shared__ int   sidx[16];
    __shared__ float sw[16];

    const int tid = threadIdx.x;
    if (tid < 4) {
        // --- projection (identical on threads 0..3, trivial cost) ---
        float rx, ry, rz;
        if (g_maskf[b * Q_ + qq] != 0.0f) {
            rx = ry = rz = -1000.0f;
        } else {
            const float* rp = refp + (b * Q_ + qq) * 3;
            rx = rp[0] * 102.4f - 51.2f;
            ry = rp[1] * 102.4f - 51.2f;
            rz = rp[2] * 102.4f - 51.2f;
        }
        const float* M = g_invext + bn * 16;
        float pch[4];
#pragma unroll
        for (int i = 0; i < 4; i++)
            pch[i] = M[i*4+0]*rx + M[i*4+1]*ry + M[i*4+2]*rz + M[i*4+3];

        float d = pch[2];
        if (isnan(d)) d = 10.0f;
        else if (isinf(d)) d = (d > 0.0f) ? 100.0f : -100.0f;
        const int invd = d < 1.5f;
        const float ds = fmaxf(d, 1.5f);
        const float pc0 = pch[0] / ds, pc1 = pch[1] / ds, pc2 = pch[2] / ds;

        const float* K = intr + bn * 9;
        float ix = K[0]*pc0 + K[1]*pc1 + K[2]*pc2;
        float iy = K[3]*pc0 + K[4]*pc1 + K[5]*pc2;
        ix = fminf(fmaxf(ix, -3000.0f), 3000.0f);
        iy = fminf(fmaxf(iy, -3000.0f), 3000.0f);

        // --- per-level corner setup ---
        const int l = tid;
        const int WFs[4] = {200, 100, 50, 25};
        const int HFs[4] = {112, 56, 28, 14};
        const float scl[4] = {0.25f, 0.125f, 0.0625f, 0.03125f};
        const int Wf = WFs[l], Hf = HFs[l];
        float gx, gy;
        if (invd) {
            gx = -100.0f; gy = -100.0f;
        } else {
            float fx = ix * scl[l];
            float fy = iy * scl[l];
            gx = fx / (float)(Wf - 1) * 2.0f - 1.0f;
            gy = fy / (float)(Hf - 1) * 2.0f - 1.0f;
            gx = fminf(fmaxf(gx, -10.0f), 10.0f);
            gy = fminf(fmaxf(gy, -10.0f), 10.0f);
        }
        float px = (gx + 1.0f) * 0.5f * (float)(Wf - 1);
        float py = (gy + 1.0f) * 0.5f * (float)(Hf - 1);
        float x0f = floorf(px), y0f = floorf(py);
        int x0 = (int)x0f, y0 = (int)y0f;
        float wx1 = px - x0f, wy1 = py - y0f;
        float wx0 = 1.0f - wx1, wy0 = 1.0f - wy1;

        int   cx[4] = {x0, x0 + 1, x0, x0 + 1};
        int   cy[4] = {y0, y0, y0 + 1, y0 + 1};
        float cw[4] = {wx0 * wy0, wx1 * wy0, wx0 * wy1, wx1 * wy1};
#pragma unroll
        for (int k = 0; k < 4; k++) {
            int xi = cx[k], yi = cy[k];
            bool valid = (xi >= 0) && (xi < Wf) && (yi >= 0) && (yi < Hf);
            int xc = min(max(xi, 0), Wf - 1);
            int yc = min(max(yi, 0), Hf - 1);
            sidx[l * 4 + k] = yc * Wf + xc;
            sw[l * 4 + k]   = valid ? cw[k] : 0.0f;
        }
    }
    __syncthreads();

    const int c = tid;
    const float* base0 = f0 + (size_t)(bn * C_ + c) * 22400;
    const float* base1 = f1 + (size_t)(bn * C_ + c) * 5600;
    const float* base2 = f2 + (size_t)(bn * C_ + c) * 1400;
    const float* base3 = f3 + (size_t)(bn * C_ + c) * 350;
    const float* bases[4] = {base0, base1, base2, base3};

    float sum = 0.0f;
#pragma unroll
    for (int l = 0; l < 4; l++) {
#pragma unroll
        for (int k = 0; k < 4; k++) {
            float w = sw[l * 4 + k];
            if (w != 0.0f) sum += w * __ldg(&bases[l][sidx[l * 4 + k]]);
        }
    }
    g_ms[(size_t)p * C_ + c] = 0.25f * sum;
}

// ---------------------------------------------------------------------------
// SGEMM 64x64 tile, TK=16, 4x4 micro, double-buffered.
// out[m, j] = (sum_k A[m,k] * W[j,k] + bias[j]) * keep[m]
// grid (4, ceil(M/64)), 256 threads. 17.4KB smem / 63 regs -> 2-3 CTAs/SM.
// ---------------------------------------------------------------------------
__global__ __launch_bounds__(256) void sgemm64(const float* __restrict__ A,
                                               const float* __restrict__ W,
                                               const float* __restrict__ bias,
                                               const float* __restrict__ keep,
                                               float* __restrict__ out, int M)
{
    __shared__ float As[2][16][68];
    __shared__ float Bs[2][16][68];

    const int tid  = threadIdx.x;
    const int row0 = blockIdx.y * 64;
    const int col0 = blockIdx.x * 64;

    const int tx = tid & 15;          // 0..15  -> cols tx*4..+3
    const int ty = tid >> 4;          // 0..15  -> rows ty*4..+3
    const int lr = tid >> 2;          // 0..63
    const int lk = (tid & 3) * 4;     // 0,4,8,12

    const int gr = row0 + lr;
    const float* Aptr = A + (size_t)gr * 256 + lk;
    const float* Wptr = W + (size_t)(col0 + lr) * 256 + lk;

    float acc[4][4];
#pragma unroll
    for (int i = 0; i < 4; i++)
#pragma unroll
        for (int j = 0; j < 4; j++) acc[i][j] = 0.0f;

    float4 av = (gr < M) ? *(const float4*)(Aptr) : make_float4(0.f,0.f,0.f,0.f);
    float4 bv = *(const float4*)(Wptr);
    As[0][lk+0][lr]=av.x; As[0][lk+1][lr]=av.y; As[0][lk+2][lr]=av.z; As[0][lk+3][lr]=av.w;
    Bs[0][lk+0][lr]=bv.x; Bs[0][lk+1][lr]=bv.y; Bs[0][lk+2][lr]=bv.z; Bs[0][lk+3][lr]=bv.w;
    __syncthreads();

#pragma unroll 1
    for (int t = 0; t < 16; t++) {
        const int buf = t & 1;
        if (t < 15) {
            const int k0 = (t + 1) * 16;
            av = (gr < M) ? *(const float4*)(Aptr + k0) : make_float4(0.f,0.f,0.f,0.f);
            bv = *(const float4*)(Wptr + k0);
        }
#pragma unroll
        for (int kk = 0; kk < 16; kk++) {
            float a[4], b[4];
            *(float4*)a = *(const float4*)&As[buf][kk][ty * 4];
            *(float4*)b = *(const float4*)&Bs[buf][kk][tx * 4];
#pragma unroll
            for (int i = 0; i < 4; i++)
#pragma unroll
                for (int j = 0; j < 4; j++) acc[i][j] += a[i] * b[j];
        }
        if (t < 15) {
            const int nb = buf ^ 1;
            As[nb][lk+0][lr]=av.x; As[nb][lk+1][lr]=av.y; As[nb][lk+2][lr]=av.z; As[nb][lk+3][lr]=av.w;
            Bs[nb][lk+0][lr]=bv.x; Bs[nb][lk+1][lr]=bv.y; Bs[nb][lk+2][lr]=bv.z; Bs[nb][lk+3][lr]=bv.w;
        }
        __syncthreads();
    }

    const float4 bias4 = *(const float4*)(bias + col0 + tx * 4);
#pragma unroll
    for (int i = 0; i < 4; i++) {
        int r = row0 + ty * 4 + i;
        if (r >= M) continue;
        float ks = keep ? keep[r] : 1.0f;
        float4 o;
        o.x = (acc[i][0] + bias4.x) * ks;
        o.y = (acc[i][1] + bias4.y) * ks;
        o.z = (acc[i][2] + bias4.z) * ks;
        o.w = (acc[i][3] + bias4.w) * ks;
        *(float4*)(out + (size_t)r * 256 + col0 + tx * 4) = o;
    }
}

// ---------------------------------------------------------------------------
// Kernel: max over cameras + fused = relu(q + max) + q  (float4-vectorized)
// ---------------------------------------------------------------------------
__global__ void maxfuse_kernel()
{
    int idx = blockIdx.x * blockDim.x + threadIdx.x;   // over BQ * C/4
    if (idx >= BQ * (C_ / 4)) return;
    int m = idx / (C_ / 4);        // b*Q + q
    int c4 = idx % (C_ / 4);
    int b = m / Q_, qq = m % Q_;

    float4 mx = make_float4(-INFINITY, -INFINITY, -INFINITY, -INFINITY);
#pragma unroll
    for (int n = 0; n < NCAM; n++) {
        const float4 v = *(const float4*)&g_v[(((size_t)(b * NCAM + n) * Q_ + qq) * C_) + c4 * 4];
        mx.x = fmaxf(mx.x, v.x); mx.y = fmaxf(mx.y, v.y);
        mx.z = fmaxf(mx.z, v.z); mx.w = fmaxf(mx.w, v.w);
    }
    const float4 qv = *(const float4*)&g_q[(size_t)m * C_ + c4 * 4];
    float4 f;
    f.x = fmaxf(qv.x + mx.x, 0.0f) + qv.x;
    f.y = fmaxf(qv.y + mx.y, 0.0f) + qv.y;
    f.z = fmaxf(qv.z + mx.z, 0.0f) + qv.z;
    f.w = fmaxf(qv.w + mx.w, 0.0f) + qv.w;
    *(float4*)&g_fused[(size_t)m * C_ + c4 * 4] = f;
}

// ---------------------------------------------------------------------------
// Launch. Side stream overlaps the q-projection GEMM with sampling + v-GEMM.
// Streams/events are created (and leaked) per call; kernel_launch only runs
// a handful of times (correctness + capture), replays execute the graph.
// ---------------------------------------------------------------------------
extern "C" void kernel_launch(void* const* d_in, const int* in_sizes, int n_in,
                              void* d_out, int out_size)
{
    const float* query = (const float*)d_in[0];
    const float* refp  = (const float*)d_in[1];
    const void*  mask  = d_in[2];
    const float* intr  = (const float*)d_in[3];
    const float* ext   = (const float*)d_in[4];
    const float* f0    = (const float*)d_in[5];
    const float* f1    = (const float*)d_in[6];
    const float* f2    = (const float*)d_in[7];
    const float* f3    = (const float*)d_in[8];
    const float* Wq    = (const float*)d_in[9];
    const float* bq    = (const float*)d_in[10];
    const float* Wv    = (const float*)d_in[11];
    const float* bv    = (const float*)d_in[12];
    const float* Wo    = (const float*)d_in[13];
    const float* bo    = (const float*)d_in[14];
    float* out = (float*)d_out;

    float *p_ms, *p_q, *p_v, *p_fused, *p_keep;
    cudaGetSymbolAddress((void**)&p_ms,    g_ms);
    cudaGetSymbolAddress((void**)&p_q,     g_q);
    cudaGetSymbolAddress((void**)&p_v,     g_v);
    cudaGetSymbolAddress((void**)&p_fused, g_fused);
    cudaGetSymbolAddress((void**)&p_keep,  g_keep);

    cudaStream_t s_side;
    cudaEvent_t ev_fork, ev_join;
    cudaStreamCreateWithFlags(&s_side, cudaStreamNonBlocking);
    cudaEventCreateWithFlags(&ev_fork, cudaEventDisableTiming);
    cudaEventCreateWithFlags(&ev_join, cudaEventDisableTiming);

    // fork: q-proj depends only on inputs
    cudaEventRecord(ev_fork, 0);
    cudaStreamWaitEvent(s_side, ev_fork, 0);
    sgemm64<<<dim3(4, (BQ + 63) / 64), 256, 0, s_side>>>(query, Wq, bq, nullptr, p_q, BQ);
    cudaEventRecord(ev_join, s_side);

    // main chain
    prep_kernel<<<1, 256>>>(mask, ext);
    sample_kernel<<<BNQ, 256>>>(refp, intr, f0, f1, f2, f3);
    // v = ms @ Wv^T + bv   (676 blocks, 2-3 CTAs/SM co-resident)
    sgemm64<<<dim3(4, (BNQ + 63) / 64), 256>>>(p_ms, Wv, bv, nullptr, p_v, BNQ);

    // join: maxfuse needs both q and v
    cudaStreamWaitEvent(0, ev_join, 0);
    maxfuse_kernel<<<(BQ * (C_ / 4) + 255) / 256, 256>>>();
    // out = (fused @ Wo^T + bo) * keep
    sgemm64<<<dim3(4, (BQ + 63) / 64), 256>>>(p_fused, Wo, bo, p_keep, out, BQ);
}

// round 13
// speedup vs baseline: 2.0981x; 1.2344x over previous
#include <cuda_runtime.h>
#include <cuda_bf16.h>
#include <math.h>

// ---------------------------------------------------------------------------
// Problem constants (fixed-shape instance)
// ---------------------------------------------------------------------------
#define B_    2
#define Q_    900
#define C_    256
#define NCAM  6
#define BQ    (B_ * Q_)          // 1800
#define BNQ   (B_ * NCAM * Q_)   // 10800

// ---------------------------------------------------------------------------
// Scratch (device globals; no dynamic allocation allowed)
// ---------------------------------------------------------------------------
__device__ float g_maskf[BQ];
__device__ float g_keep[BQ];
__device__ float g_invext[B_ * NCAM * 16];
__device__ __align__(16) __nv_bfloat16 g_ms_hi[BNQ * C_];   // 5.5 MB
__device__ __align__(16) __nv_bfloat16 g_ms_lo[BNQ * C_];
__device__ __align__(16) float g_q[BQ * C_];
__device__ __align__(16) float g_v[BNQ * C_];               // 11 MB
__device__ __align__(16) __nv_bfloat16 g_fu_hi[BQ * C_];
__device__ __align__(16) __nv_bfloat16 g_fu_lo[BQ * C_];
__device__ __align__(16) __nv_bfloat16 g_wv_hi[C_ * C_], g_wv_lo[C_ * C_];
__device__ __align__(16) __nv_bfloat16 g_wo_hi[C_ * C_], g_wo_lo[C_ * C_];

// ---------------------------------------------------------------------------
// MMA helpers (sm_80+ HMMA bf16, fp32 accumulate)
// ---------------------------------------------------------------------------
__device__ __forceinline__ void ldsm4(unsigned* r, unsigned addr) {
    asm volatile("ldmatrix.sync.aligned.m8n8.x4.shared.b16 {%0,%1,%2,%3}, [%4];"
        : "=r"(r[0]), "=r"(r[1]), "=r"(r[2]), "=r"(r[3]) : "r"(addr));
}
__device__ __forceinline__ void mma16816(float* c, const unsigned* a, const unsigned* b) {
    asm volatile(
        "mma.sync.aligned.m16n8k16.row.col.f32.bf16.bf16.f32 "
        "{%0,%1,%2,%3}, {%4,%5,%6,%7}, {%8,%9}, {%0,%1,%2,%3};"
        : "+f"(c[0]), "+f"(c[1]), "+f"(c[2]), "+f"(c[3])
        : "r"(a[0]), "r"(a[1]), "r"(a[2]), "r"(a[3]), "r"(b[0]), "r"(b[1]));
}
__device__ __forceinline__ void split_bf16(float v, __nv_bfloat16& hi, __nv_bfloat16& lo) {
    hi = __float2bfloat16(v);
    lo = __float2bfloat16(v - __bfloat162float(hi));
}

// ---------------------------------------------------------------------------
// Kernel 1: mask dtype detection + mask arrays + 4x4 extrinsic inverses
// ---------------------------------------------------------------------------
__global__ void prep_kernel(const void* __restrict__ mask_raw,
                            const float* __restrict__ ext)
{
    __shared__ int s_byte;
    if (threadIdx.x == 0) s_byte = 0;
    __syncthreads();

    const unsigned int* w = (const unsigned int*)mask_raw;
    for (int i = threadIdx.x; i < 450; i += blockDim.x) {
        unsigned int x = w[i];
        if (x != 0u && x != 1u && x != 0x3F800000u) atomicOr(&s_byte, 1);
    }
    __syncthreads();
    const bool isbyte = (s_byte != 0);
    const unsigned char* bytes = (const unsigned char*)mask_raw;
    for (int i = threadIdx.x; i < BQ; i += blockDim.x) {
        bool mk = isbyte ? (bytes[i] != 0) : (w[i] != 0u);
        g_maskf[i] = mk ? 1.0f : 0.0f;
        g_keep[i]  = mk ? 0.0f : 1.0f;
    }

    int t = threadIdx.x;
    if (t < B_ * NCAM) {
        double a[4][8];
        for (int i = 0; i < 4; i++) {
            for (int j = 0; j < 4; j++) {
                a[i][j]     = (double)ext[t * 16 + i * 4 + j];
                a[i][4 + j] = (i == j) ? 1.0 : 0.0;
            }
        }
        for (int col = 0; col < 4; col++) {
            int piv = col; double best = fabs(a[col][col]);
            for (int r = col + 1; r < 4; r++) {
                double v = fabs(a[r][col]);
                if (v > best) { best = v; piv = r; }
            }
            if (piv != col) {
                for (int j = 0; j < 8; j++) { double tmp = a[col][j]; a[col][j] = a[piv][j]; a[piv][j] = tmp; }
            }
            double d = a[col][col];
            for (int j = 0; j < 8; j++) a[col][j] /= d;
            for (int r = 0; r < 4; r++) {
                if (r == col) continue;
                double f = a[r][col];
                for (int j = 0; j < 8; j++) a[r][j] -= f * a[col][j];
            }
        }
        for (int i = 0; i < 4; i++) {
            for (int j = 0; j < 4; j++) {
                float v = (float)a[i][4 + j];
                if (isnan(v)) v = 0.0f;
                else if (isinf(v)) v = (v > 0.0f) ? 1e6f : -1e6f;
                g_invext[t * 16 + i * 4 + j] = v;
            }
        }
    }
}

// ---------------------------------------------------------------------------
// Kernel: weight fp32 -> bf16 hi/lo split (65536 elements)
// ---------------------------------------------------------------------------
__global__ void wconv_kernel(const float* __restrict__ src,
                             __nv_bfloat16* __restrict__ hi,
                             __nv_bfloat16* __restrict__ lo)
{
    int i = blockIdx.x * 256 + threadIdx.x;
    float v = src[i];
    __nv_bfloat16 h, l;
    split_bf16(v, h, l);
    hi[i] = h; lo[i] = l;
}

// ---------------------------------------------------------------------------
// Kernel 2: projection + bilinear sampling (fused), emits bf16 hi/lo
// ---------------------------------------------------------------------------
__global__ void sample_kernel(const float* __restrict__ refp,
                              const float* __restrict__ intr,
                              const float* __restrict__ f0,
                              const float* __restrict__ f1,
                              const float* __restrict__ f2,
                              const float* __restrict__ f3)
{
    const int p  = blockIdx.x;       // (b*N+n)*Q + q
    const int bn = p / Q_;
    const int qq = p % Q_;
    const int b  = bn / NCAM;

    __shared__ int   sidx[16];
    __shared__ float sw[16];

    const int tid = threadIdx.x;
    if (tid < 4) {
        float rx, ry, rz;
        if (g_maskf[b * Q_ + qq] != 0.0f) {
            rx = ry = rz = -1000.0f;
        } else {
            const float* rp = refp + (b * Q_ + qq) * 3;
            rx = rp[0] * 102.4f - 51.2f;
            ry = rp[1] * 102.4f - 51.2f;
            rz = rp[2] * 102.4f - 51.2f;
        }
        const float* M = g_invext + bn * 16;
        float pch[4];
#pragma unroll
        for (int i = 0; i < 4; i++)
            pch[i] = M[i*4+0]*rx + M[i*4+1]*ry + M[i*4+2]*rz + M[i*4+3];

        float d = pch[2];
        if (isnan(d)) d = 10.0f;
        else if (isinf(d)) d = (d > 0.0f) ? 100.0f : -100.0f;
        const int invd = d < 1.5f;
        const float ds = fmaxf(d, 1.5f);
        const float pc0 = pch[0] / ds, pc1 = pch[1] / ds, pc2 = pch[2] / ds;

        const float* K = intr + bn * 9;
        float ix = K[0]*pc0 + K[1]*pc1 + K[2]*pc2;
        float iy = K[3]*pc0 + K[4]*pc1 + K[5]*pc2;
        ix = fminf(fmaxf(ix, -3000.0f), 3000.0f);
        iy = fminf(fmaxf(iy, -3000.0f), 3000.0f);

        const int l = tid;
        const int WFs[4] = {200, 100, 50, 25};
        const int HFs[4] = {112, 56, 28, 14};
        const float scl[4] = {0.25f, 0.125f, 0.0625f, 0.03125f};
        const int Wf = WFs[l], Hf = HFs[l];
        float gx, gy;
        if (invd) {
            gx = -100.0f; gy = -100.0f;
        } else {
            float fx = ix * scl[l];
            float fy = iy * scl[l];
            gx = fx / (float)(Wf - 1) * 2.0f - 1.0f;
            gy = fy / (float)(Hf - 1) * 2.0f - 1.0f;
            gx = fminf(fmaxf(gx, -10.0f), 10.0f);
            gy = fminf(fmaxf(gy, -10.0f), 10.0f);
        }
        float px = (gx + 1.0f) * 0.5f * (float)(Wf - 1);
        float py = (gy + 1.0f) * 0.5f * (float)(Hf - 1);
        float x0f = floorf(px), y0f = floorf(py);
        int x0 = (int)x0f, y0 = (int)y0f;
        float wx1 = px - x0f, wy1 = py - y0f;
        float wx0 = 1.0f - wx1, wy0 = 1.0f - wy1;

        int   cx[4] = {x0, x0 + 1, x0, x0 + 1};
        int   cy[4] = {y0, y0, y0 + 1, y0 + 1};
        float cw[4] = {wx0 * wy0, wx1 * wy0, wx0 * wy1, wx1 * wy1};
#pragma unroll
        for (int k = 0; k < 4; k++) {
            int xi = cx[k], yi = cy[k];
            bool valid = (xi >= 0) && (xi < Wf) && (yi >= 0) && (yi < Hf);
            int xc = min(max(xi, 0), Wf - 1);
            int yc = min(max(yi, 0), Hf - 1);
            sidx[l * 4 + k] = yc * Wf + xc;
            sw[l * 4 + k]   = valid ? cw[k] : 0.0f;
        }
    }
    __syncthreads();

    const int c = tid;
    const float* base0 = f0 + (size_t)(bn * C_ + c) * 22400;
    const float* base1 = f1 + (size_t)(bn * C_ + c) * 5600;
    const float* base2 = f2 + (size_t)(bn * C_ + c) * 1400;
    const float* base3 = f3 + (size_t)(bn * C_ + c) * 350;
    const float* bases[4] = {base0, base1, base2, base3};

    float sum = 0.0f;
#pragma unroll
    for (int l = 0; l < 4; l++) {
#pragma unroll
        for (int k = 0; k < 4; k++) {
            float w = sw[l * 4 + k];
            if (w != 0.0f) sum += w * __ldg(&bases[l][sidx[l * 4 + k]]);
        }
    }
    float v = 0.25f * sum;
    __nv_bfloat16 hi, lo;
    split_bf16(v, hi, lo);
    const size_t off = (size_t)p * C_ + c;
    g_ms_hi[off] = hi;
    g_ms_lo[off] = lo;
}

// ---------------------------------------------------------------------------
// Tensor-core GEMM (bf16x3 decomposition, fp32 accumulate):
// out[m, j] = (sum_k A[m,k] * W[j,k] + bias[j]) * keep[m]
// A given as hi/lo bf16 [M][256]; W as hi/lo bf16 [256][256] (k contiguous).
// Block 128(M) x 64(N), 8 warps, warp tile 32x32 (2 m16 x 4 n8 frags).
// grid (4, ceil(M/128)). K-chunks of 16, double-buffered smem (36 KB).
// ---------------------------------------------------------------------------
#define KSTR 24   // smem row stride in bf16 (48B: 16B-aligned, ldmatrix conflict-free)

__global__ __launch_bounds__(256) void mma_gemm(
    const __nv_bfloat16* __restrict__ Ahi, const __nv_bfloat16* __restrict__ Alo,
    const __nv_bfloat16* __restrict__ Bhi, const __nv_bfloat16* __restrict__ Blo,
    const float* __restrict__ bias, const float* __restrict__ keep,
    float* __restrict__ out, int M)
{
    __shared__ __align__(16) __nv_bfloat16 sA[2][2][128 * KSTR];
    __shared__ __align__(16) __nv_bfloat16 sB[2][2][64 * KSTR];

    const int tid  = threadIdx.x;
    const int lane = tid & 31, warp = tid >> 5;
    const int wm = warp & 3, wn = warp >> 2;
    const int row0 = blockIdx.y * 128, col0 = blockIdx.x * 64;

    // global->smem load mapping (one uint4 = 8 bf16 per thread per matrix)
    const int ar = tid >> 1;                 // 0..127
    const int ak = (tid & 1) * 8;            // 0 / 8
    const int garow = min(row0 + ar, M - 1);
    const __nv_bfloat16* pAhi = Ahi + (size_t)garow * 256 + ak;
    const __nv_bfloat16* pAlo = Alo + (size_t)garow * 256 + ak;
    const int bsel = tid >> 7;               // 0: hi, 1: lo
    const int br = (tid & 127) >> 1;         // 0..63
    const int bk = (tid & 1) * 8;
    const __nv_bfloat16* pB = (bsel ? Blo : Bhi) + (size_t)(col0 + br) * 256 + bk;

    const int sa_off = ar * KSTR + ak;
    const int sb_off = br * KSTR + bk;

    float acc[2][4][4];
#pragma unroll
    for (int i = 0; i < 2; i++)
#pragma unroll
        for (int j = 0; j < 4; j++)
#pragma unroll
            for (int k = 0; k < 4; k++) acc[i][j][k] = 0.0f;

    uint4 ah = *(const uint4*)pAhi;
    uint4 al = *(const uint4*)pAlo;
    uint4 bb = *(const uint4*)pB;
    *(uint4*)&sA[0][0][sa_off] = ah;
    *(uint4*)&sA[0][1][sa_off] = al;
    *(uint4*)&sB[0][bsel][sb_off] = bb;
    __syncthreads();

    // ldmatrix per-thread tile coordinates
    const int a_r = lane & 15;               // row within m16 tile
    const int a_c = (lane >> 4) * 8;         // k-offset 0/8
    const int b_n = (lane & 7) + ((lane & 16) ? 8 : 0);
    const int b_k = (lane & 8) ? 8 : 0;

#pragma unroll 1
    for (int t = 0; t < 16; t++) {
        const int buf = t & 1;
        if (t < 15) {
            const int k0 = (t + 1) * 16;
            ah = *(const uint4*)(pAhi + k0);
            al = *(const uint4*)(pAlo + k0);
            bb = *(const uint4*)(pB + k0);
        }

        unsigned afh[2][4], afl[2][4], bfh[2][4], bfl[2][4];
#pragma unroll
        for (int mf = 0; mf < 2; mf++) {
            const int rbase = (wm * 32 + mf * 16 + a_r) * KSTR + a_c;
            ldsm4(afh[mf], (unsigned)__cvta_generic_to_shared(&sA[buf][0][rbase]));
            ldsm4(afl[mf], (unsigned)__cvta_generic_to_shared(&sA[buf][1][rbase]));
        }
#pragma unroll
        for (int nf2 = 0; nf2 < 2; nf2++) {
            const int nbase = (wn * 32 + nf2 * 16 + b_n) * KSTR + b_k;
            ldsm4(bfh[nf2], (unsigned)__cvta_generic_to_shared(&sB[buf][0][nbase]));
            ldsm4(bfl[nf2], (unsigned)__cvta_generic_to_shared(&sB[buf][1][nbase]));
        }
#pragma unroll
        for (int mf = 0; mf < 2; mf++)
#pragma unroll
            for (int nf = 0; nf < 4; nf++) {
                const int nf2 = nf >> 1, h = (nf & 1) * 2;
                mma16816(acc[mf][nf], afh[mf], &bfh[nf2][h]);   // hi*hi
                mma16816(acc[mf][nf], afh[mf], &bfl[nf2][h]);   // hi*lo
                mma16816(acc[mf][nf], afl[mf], &bfh[nf2][h]);   // lo*hi
            }

        if (t < 15) {
            const int nb = buf ^ 1;
            *(uint4*)&sA[nb][0][sa_off] = ah;
            *(uint4*)&sA[nb][1][sa_off] = al;
            *(uint4*)&sB[nb][bsel][sb_off] = bb;
        }
        __syncthreads();
    }

    // epilogue: c0,c1 -> (row, col..col+1); c2,c3 -> (row+8, ...)
#pragma unroll
    for (int mf = 0; mf < 2; mf++)
#pragma unroll
        for (int nf = 0; nf < 4; nf++) {
            const int r  = row0 + wm * 32 + mf * 16 + (lane >> 2);
            const int cg = col0 + wn * 32 + nf * 8 + (lane & 3) * 2;
            const float b0v = bias[cg], b1v = bias[cg + 1];
            if (r < M) {
                const float ks = keep ? keep[r] : 1.0f;
                float2 o = make_float2((acc[mf][nf][0] + b0v) * ks,
                                       (acc[mf][nf][1] + b1v) * ks);
                *(float2*)(out + (size_t)r * 256 + cg) = o;
            }
            const int r2 = r + 8;
            if (r2 < M) {
                const float ks = keep ? keep[r2] : 1.0f;
                float2 o = make_float2((acc[mf][nf][2] + b0v) * ks,
                                       (acc[mf][nf][3] + b1v) * ks);
                *(float2*)(out + (size_t)r2 * 256 + cg) = o;
            }
        }
}

// ---------------------------------------------------------------------------
// SGEMM 64x64 (fp32 SIMT) — kept for the fully-overlapped q projection
// ---------------------------------------------------------------------------
__global__ __launch_bounds__(256) void sgemm64(const float* __restrict__ A,
                                               const float* __restrict__ W,
                                               const float* __restrict__ bias,
                                               const float* __restrict__ keep,
                                               float* __restrict__ out, int M)
{
    __shared__ float As[2][16][68];
    __shared__ float Bs[2][16][68];

    const int tid  = threadIdx.x;
    const int row0 = blockIdx.y * 64;
    const int col0 = blockIdx.x * 64;

    const int tx = tid & 15;
    const int ty = tid >> 4;
    const int lr = tid >> 2;
    const int lk = (tid & 3) * 4;

    const int gr = row0 + lr;
    const float* Aptr = A + (size_t)gr * 256 + lk;
    const float* Wptr = W + (size_t)(col0 + lr) * 256 + lk;

    float acc[4][4];
#pragma unroll
    for (int i = 0; i < 4; i++)
#pragma unroll
        for (int j = 0; j < 4; j++) acc[i][j] = 0.0f;

    float4 av = (gr < M) ? *(const float4*)(Aptr) : make_float4(0.f,0.f,0.f,0.f);
    float4 bv = *(const float4*)(Wptr);
    As[0][lk+0][lr]=av.x; As[0][lk+1][lr]=av.y; As[0][lk+2][lr]=av.z; As[0][lk+3][lr]=av.w;
    Bs[0][lk+0][lr]=bv.x; Bs[0][lk+1][lr]=bv.y; Bs[0][lk+2][lr]=bv.z; Bs[0][lk+3][lr]=bv.w;
    __syncthreads();

#pragma unroll 1
    for (int t = 0; t < 16; t++) {
        const int buf = t & 1;
        if (t < 15) {
            const int k0 = (t + 1) * 16;
            av = (gr < M) ? *(const float4*)(Aptr + k0) : make_float4(0.f,0.f,0.f,0.f);
            bv = *(const float4*)(Wptr + k0);
        }
#pragma unroll
        for (int kk = 0; kk < 16; kk++) {
            float a[4], b[4];
            *(float4*)a = *(const float4*)&As[buf][kk][ty * 4];
            *(float4*)b = *(const float4*)&Bs[buf][kk][tx * 4];
#pragma unroll
            for (int i = 0; i < 4; i++)
#pragma unroll
                for (int j = 0; j < 4; j++) acc[i][j] += a[i] * b[j];
        }
        if (t < 15) {
            const int nb = buf ^ 1;
            As[nb][lk+0][lr]=av.x; As[nb][lk+1][lr]=av.y; As[nb][lk+2][lr]=av.z; As[nb][lk+3][lr]=av.w;
            Bs[nb][lk+0][lr]=bv.x; Bs[nb][lk+1][lr]=bv.y; Bs[nb][lk+2][lr]=bv.z; Bs[nb][lk+3][lr]=bv.w;
        }
        __syncthreads();
    }

    const float4 bias4 = *(const float4*)(bias + col0 + tx * 4);
#pragma unroll
    for (int i = 0; i < 4; i++) {
        int r = row0 + ty * 4 + i;
        if (r >= M) continue;
        float ks = keep ? keep[r] : 1.0f;
        float4 o;
        o.x = (acc[i][0] + bias4.x) * ks;
        o.y = (acc[i][1] + bias4.y) * ks;
        o.z = (acc[i][2] + bias4.z) * ks;
        o.w = (acc[i][3] + bias4.w) * ks;
        *(float4*)(out + (size_t)r * 256 + col0 + tx * 4) = o;
    }
}

// ---------------------------------------------------------------------------
// Kernel: max over cameras + fused = relu(q + max) + q; emits bf16 hi/lo
// ---------------------------------------------------------------------------
__global__ void maxfuse_kernel()
{
    int idx = blockIdx.x * blockDim.x + threadIdx.x;   // over BQ * C/4
    if (idx >= BQ * (C_ / 4)) return;
    int m = idx / (C_ / 4);        // b*Q + q
    int c4 = idx % (C_ / 4);
    int b = m / Q_, qq = m % Q_;

    float4 mx = make_float4(-INFINITY, -INFINITY, -INFINITY, -INFINITY);
#pragma unroll
    for (int n = 0; n < NCAM; n++) {
        const float4 v = *(const float4*)&g_v[(((size_t)(b * NCAM + n) * Q_ + qq) * C_) + c4 * 4];
        mx.x = fmaxf(mx.x, v.x); mx.y = fmaxf(mx.y, v.y);
        mx.z = fmaxf(mx.z, v.z); mx.w = fmaxf(mx.w, v.w);
    }
    const float4 qv = *(const float4*)&g_q[(size_t)m * C_ + c4 * 4];
    float f[4];
    f[0] = fmaxf(qv.x + mx.x, 0.0f) + qv.x;
    f[1] = fmaxf(qv.y + mx.y, 0.0f) + qv.y;
    f[2] = fmaxf(qv.z + mx.z, 0.0f) + qv.z;
    f[3] = fmaxf(qv.w + mx.w, 0.0f) + qv.w;
    const size_t off = (size_t)m * C_ + c4 * 4;
#pragma unroll
    for (int i = 0; i < 4; i++) {
        __nv_bfloat16 hi, lo;
        split_bf16(f[i], hi, lo);
        g_fu_hi[off + i] = hi;
        g_fu_lo[off + i] = lo;
    }
}

// ---------------------------------------------------------------------------
// Launch. Side stream: weight splits + q-projection GEMM, overlapped with
// prep/sample/v-GEMM on the main stream.
// ---------------------------------------------------------------------------
extern "C" void kernel_launch(void* const* d_in, const int* in_sizes, int n_in,
                              void* d_out, int out_size)
{
    const float* query = (const float*)d_in[0];
    const float* refp  = (const float*)d_in[1];
    const void*  mask  = d_in[2];
    const float* intr  = (const float*)d_in[3];
    const float* ext   = (const float*)d_in[4];
    const float* f0    = (const float*)d_in[5];
    const float* f1    = (const float*)d_in[6];
    const float* f2    = (const float*)d_in[7];
    const float* f3    = (const float*)d_in[8];
    const float* Wq    = (const float*)d_in[9];
    const float* bq    = (const float*)d_in[10];
    const float* Wv    = (const float*)d_in[11];
    const float* bv    = (const float*)d_in[12];
    const float* Wo    = (const float*)d_in[13];
    const float* bo    = (const float*)d_in[14];
    float* out = (float*)d_out;

    float *p_q, *p_v, *p_keep;
    __nv_bfloat16 *p_ms_hi, *p_ms_lo, *p_fu_hi, *p_fu_lo;
    __nv_bfloat16 *p_wv_hi, *p_wv_lo, *p_wo_hi, *p_wo_lo;
    cudaGetSymbolAddress((void**)&p_q,     g_q);
    cudaGetSymbolAddress((void**)&p_v,     g_v);
    cudaGetSymbolAddress((void**)&p_keep,  g_keep);
    cudaGetSymbolAddress((void**)&p_ms_hi, g_ms_hi);
    cudaGetSymbolAddress((void**)&p_ms_lo, g_ms_lo);
    cudaGetSymbolAddress((void**)&p_fu_hi, g_fu_hi);
    cudaGetSymbolAddress((void**)&p_fu_lo, g_fu_lo);
    cudaGetSymbolAddress((void**)&p_wv_hi, g_wv_hi);
    cudaGetSymbolAddress((void**)&p_wv_lo, g_wv_lo);
    cudaGetSymbolAddress((void**)&p_wo_hi, g_wo_hi);
    cudaGetSymbolAddress((void**)&p_wo_lo, g_wo_lo);

    cudaStream_t s_side;
    cudaEvent_t ev_fork, ev_w, ev_join;
    cudaStreamCreateWithFlags(&s_side, cudaStreamNonBlocking);
    cudaEventCreateWithFlags(&ev_fork, cudaEventDisableTiming);
    cudaEventCreateWithFlags(&ev_w,    cudaEventDisableTiming);
    cudaEventCreateWithFlags(&ev_join, cudaEventDisableTiming);

    // side stream: weight splits, then q-proj
    cudaEventRecord(ev_fork, 0);
    cudaStreamWaitEvent(s_side, ev_fork, 0);
    wconv_kernel<<<256, 256, 0, s_side>>>(Wv, p_wv_hi, p_wv_lo);
    wconv_kernel<<<256, 256, 0, s_side>>>(Wo, p_wo_hi, p_wo_lo);
    cudaEventRecord(ev_w, s_side);
    sgemm64<<<dim3(4, (BQ + 63) / 64), 256, 0, s_side>>>(query, Wq, bq, nullptr, p_q, BQ);
    cudaEventRecord(ev_join, s_side);

    // main chain
    prep_kernel<<<1, 256>>>(mask, ext);
    sample_kernel<<<BNQ, 256>>>(refp, intr, f0, f1, f2, f3);

    // v = ms @ Wv^T + bv  (tensor cores, 340 blocks)
    cudaStreamWaitEvent(0, ev_w, 0);
    mma_gemm<<<dim3(4, (BNQ + 127) / 128), 256>>>(p_ms_hi, p_ms_lo, p_wv_hi, p_wv_lo,
                                                  bv, nullptr, p_v, BNQ);

    // join q, then fuse
    cudaStreamWaitEvent(0, ev_join, 0);
    maxfuse_kernel<<<(BQ * (C_ / 4) + 255) / 256, 256>>>();

    // out = (fused @ Wo^T + bo) * keep  (tensor cores, 60 blocks)
    mma_gemm<<<dim3(4, (BQ + 127) / 128), 256>>>(p_fu_hi, p_fu_lo, p_wo_hi, p_wo_lo,
                                                 bo, p_keep, out, BQ);
}

// round 14
// speedup vs baseline: 2.2252x; 1.0606x over previous
#include <cuda_runtime.h>
#include <cuda_bf16.h>
#include <math.h>

// ---------------------------------------------------------------------------
// Problem constants (fixed-shape instance)
// ---------------------------------------------------------------------------
#define B_    2
#define Q_    900
#define C_    256
#define NCAM  6
#define BQ    (B_ * Q_)          // 1800
#define BNQ   (B_ * NCAM * Q_)   // 10800

// ---------------------------------------------------------------------------
// Scratch (device globals; no dynamic allocation allowed)
// ---------------------------------------------------------------------------
__device__ float g_maskf[BQ];
__device__ float g_keep[BQ];
__device__ float g_invext[B_ * NCAM * 16];
__device__ __align__(16) __nv_bfloat16 g_ms_hi[BNQ * C_];   // 5.5 MB
__device__ __align__(16) __nv_bfloat16 g_ms_lo[BNQ * C_];
__device__ __align__(16) float g_q[BQ * C_];
__device__ __align__(16) float g_v[BNQ * C_];               // 11 MB
__device__ __align__(16) __nv_bfloat16 g_fu_hi[BQ * C_];
__device__ __align__(16) __nv_bfloat16 g_fu_lo[BQ * C_];
__device__ __align__(16) __nv_bfloat16 g_wv_hi[C_ * C_], g_wv_lo[C_ * C_];
__device__ __align__(16) __nv_bfloat16 g_wo_hi[C_ * C_], g_wo_lo[C_ * C_];

// ---------------------------------------------------------------------------
// MMA helpers (sm_80+ HMMA bf16, fp32 accumulate)
// ---------------------------------------------------------------------------
__device__ __forceinline__ void ldsm4(unsigned* r, unsigned addr) {
    asm volatile("ldmatrix.sync.aligned.m8n8.x4.shared.b16 {%0,%1,%2,%3}, [%4];"
        : "=r"(r[0]), "=r"(r[1]), "=r"(r[2]), "=r"(r[3]) : "r"(addr));
}
__device__ __forceinline__ void mma16816(float* c, const unsigned* a, const unsigned* b) {
    asm volatile(
        "mma.sync.aligned.m16n8k16.row.col.f32.bf16.bf16.f32 "
        "{%0,%1,%2,%3}, {%4,%5,%6,%7}, {%8,%9}, {%0,%1,%2,%3};"
        : "+f"(c[0]), "+f"(c[1]), "+f"(c[2]), "+f"(c[3])
        : "r"(a[0]), "r"(a[1]), "r"(a[2]), "r"(a[3]), "r"(b[0]), "r"(b[1]));
}
__device__ __forceinline__ void split_bf16(float v, __nv_bfloat16& hi, __nv_bfloat16& lo) {
    hi = __float2bfloat16(v);
    lo = __float2bfloat16(v - __bfloat162float(hi));
}

// ---------------------------------------------------------------------------
// Kernel 1: mask dtype detection + mask arrays + 4x4 extrinsic inverses
// (adjugate/cofactor closed form in fp64: ~5-deep dependency chain instead
//  of serial Gauss-Jordan -> was 23.8us, now latency-trivial)
// ---------------------------------------------------------------------------
__global__ void prep_kernel(const void* __restrict__ mask_raw,
                            const float* __restrict__ ext)
{
    __shared__ int s_byte;
    if (threadIdx.x == 0) s_byte = 0;
    __syncthreads();

    const unsigned int* w = (const unsigned int*)mask_raw;
    for (int i = threadIdx.x; i < 450; i += blockDim.x) {
        unsigned int x = w[i];
        if (x != 0u && x != 1u && x != 0x3F800000u) atomicOr(&s_byte, 1);
    }
    __syncthreads();
    const bool isbyte = (s_byte != 0);
    const unsigned char* bytes = (const unsigned char*)mask_raw;
    for (int i = threadIdx.x; i < BQ; i += blockDim.x) {
        bool mk = isbyte ? (bytes[i] != 0) : (w[i] != 0u);
        g_maskf[i] = mk ? 1.0f : 0.0f;
        g_keep[i]  = mk ? 0.0f : 1.0f;
    }

    int t = threadIdx.x;
    if (t < B_ * NCAM) {
        double m[16], inv[16];
#pragma unroll
        for (int i = 0; i < 16; i++) m[i] = (double)ext[t * 16 + i];

        inv[0]  =  m[5]*m[10]*m[15] - m[5]*m[11]*m[14] - m[9]*m[6]*m[15]
                 + m[9]*m[7]*m[14] + m[13]*m[6]*m[11] - m[13]*m[7]*m[10];
        inv[4]  = -m[4]*m[10]*m[15] + m[4]*m[11]*m[14] + m[8]*m[6]*m[15]
                 - m[8]*m[7]*m[14] - m[12]*m[6]*m[11] + m[12]*m[7]*m[10];
        inv[8]  =  m[4]*m[9]*m[15] - m[4]*m[11]*m[13] - m[8]*m[5]*m[15]
                 + m[8]*m[7]*m[13] + m[12]*m[5]*m[11] - m[12]*m[7]*m[9];
        inv[12] = -m[4]*m[9]*m[14] + m[4]*m[10]*m[13] + m[8]*m[5]*m[14]
                 - m[8]*m[6]*m[13] - m[12]*m[5]*m[10] + m[12]*m[6]*m[9];
        inv[1]  = -m[1]*m[10]*m[15] + m[1]*m[11]*m[14] + m[9]*m[2]*m[15]
                 - m[9]*m[3]*m[14] - m[13]*m[2]*m[11] + m[13]*m[3]*m[10];
        inv[5]  =  m[0]*m[10]*m[15] - m[0]*m[11]*m[14] - m[8]*m[2]*m[15]
                 + m[8]*m[3]*m[14] + m[12]*m[2]*m[11] - m[12]*m[3]*m[10];
        inv[9]  = -m[0]*m[9]*m[15] + m[0]*m[11]*m[13] + m[8]*m[1]*m[15]
                 - m[8]*m[3]*m[13] - m[12]*m[1]*m[11] + m[12]*m[3]*m[9];
        inv[13] =  m[0]*m[9]*m[14] - m[0]*m[10]*m[13] - m[8]*m[1]*m[14]
                 + m[8]*m[2]*m[13] + m[12]*m[1]*m[10] - m[12]*m[2]*m[9];
        inv[2]  =  m[1]*m[6]*m[15] - m[1]*m[7]*m[14] - m[5]*m[2]*m[15]
                 + m[5]*m[3]*m[14] + m[13]*m[2]*m[7] - m[13]*m[3]*m[6];
        inv[6]  = -m[0]*m[6]*m[15] + m[0]*m[7]*m[14] + m[4]*m[2]*m[15]
                 - m[4]*m[3]*m[14] - m[12]*m[2]*m[7] + m[12]*m[3]*m[6];
        inv[10] =  m[0]*m[5]*m[15] - m[0]*m[7]*m[13] - m[4]*m[1]*m[15]
                 + m[4]*m[3]*m[13] + m[12]*m[1]*m[7] - m[12]*m[3]*m[5];
        inv[14] = -m[0]*m[5]*m[14] + m[0]*m[6]*m[13] + m[4]*m[1]*m[14]
                 - m[4]*m[2]*m[13] - m[12]*m[1]*m[6] + m[12]*m[2]*m[5];
        inv[3]  = -m[1]*m[6]*m[11] + m[1]*m[7]*m[10] + m[5]*m[2]*m[11]
                 - m[5]*m[3]*m[10] - m[9]*m[2]*m[7] + m[9]*m[3]*m[6];
        inv[7]  =  m[0]*m[6]*m[11] - m[0]*m[7]*m[10] - m[4]*m[2]*m[11]
                 + m[4]*m[3]*m[10] + m[8]*m[2]*m[7] - m[8]*m[3]*m[6];
        inv[11] = -m[0]*m[5]*m[11] + m[0]*m[7]*m[9] + m[4]*m[1]*m[11]
                 - m[4]*m[3]*m[9] - m[8]*m[1]*m[7] + m[8]*m[3]*m[5];
        inv[15] =  m[0]*m[5]*m[10] - m[0]*m[6]*m[9] - m[4]*m[1]*m[10]
                 + m[4]*m[2]*m[9] + m[8]*m[1]*m[6] - m[8]*m[2]*m[5];

        double det = m[0]*inv[0] + m[1]*inv[4] + m[2]*inv[8] + m[3]*inv[12];
        double rdet = 1.0 / det;
#pragma unroll
        for (int i = 0; i < 16; i++) {
            float v = (float)(inv[i] * rdet);
            if (isnan(v)) v = 0.0f;
            else if (isinf(v)) v = (v > 0.0f) ? 1e6f : -1e6f;
            g_invext[t * 16 + i] = v;
        }
    }
}

// ---------------------------------------------------------------------------
// Kernel: weight fp32 -> bf16 hi/lo split (65536 elements)
// ---------------------------------------------------------------------------
__global__ void wconv_kernel(const float* __restrict__ src,
                             __nv_bfloat16* __restrict__ hi,
                             __nv_bfloat16* __restrict__ lo)
{
    int i = blockIdx.x * 256 + threadIdx.x;
    float v = src[i];
    __nv_bfloat16 h, l;
    split_bf16(v, h, l);
    hi[i] = h; lo[i] = l;
}

// ---------------------------------------------------------------------------
// Kernel 2: projection + bilinear sampling (fused), emits bf16 hi/lo
// ---------------------------------------------------------------------------
__global__ void sample_kernel(const float* __restrict__ refp,
                              const float* __restrict__ intr,
                              const float* __restrict__ f0,
                              const float* __restrict__ f1,
                              const float* __restrict__ f2,
                              const float* __restrict__ f3)
{
    const int p  = blockIdx.x;       // (b*N+n)*Q + q
    const int bn = p / Q_;
    const int qq = p % Q_;
    const int b  = bn / NCAM;

    __shared__ int   sidx[16];
    __shared__ float sw[16];

    const int tid = threadIdx.x;
    if (tid < 4) {
        float rx, ry, rz;
        if (g_maskf[b * Q_ + qq] != 0.0f) {
            rx = ry = rz = -1000.0f;
        } else {
            const float* rp = refp + (b * Q_ + qq) * 3;
            rx = rp[0] * 102.4f - 51.2f;
            ry = rp[1] * 102.4f - 51.2f;
            rz = rp[2] * 102.4f - 51.2f;
        }
        const float* M = g_invext + bn * 16;
        float pch[4];
#pragma unroll
        for (int i = 0; i < 4; i++)
            pch[i] = M[i*4+0]*rx + M[i*4+1]*ry + M[i*4+2]*rz + M[i*4+3];

        float d = pch[2];
        if (isnan(d)) d = 10.0f;
        else if (isinf(d)) d = (d > 0.0f) ? 100.0f : -100.0f;
        const int invd = d < 1.5f;
        const float ds = fmaxf(d, 1.5f);
        const float pc0 = pch[0] / ds, pc1 = pch[1] / ds, pc2 = pch[2] / ds;

        const float* K = intr + bn * 9;
        float ix = K[0]*pc0 + K[1]*pc1 + K[2]*pc2;
        float iy = K[3]*pc0 + K[4]*pc1 + K[5]*pc2;
        ix = fminf(fmaxf(ix, -3000.0f), 3000.0f);
        iy = fminf(fmaxf(iy, -3000.0f), 3000.0f);

        const int l = tid;
        const int WFs[4] = {200, 100, 50, 25};
        const int HFs[4] = {112, 56, 28, 14};
        const float scl[4] = {0.25f, 0.125f, 0.0625f, 0.03125f};
        const int Wf = WFs[l], Hf = HFs[l];
        float gx, gy;
        if (invd) {
            gx = -100.0f; gy = -100.0f;
        } else {
            float fx = ix * scl[l];
            float fy = iy * scl[l];
            gx = fx / (float)(Wf - 1) * 2.0f - 1.0f;
            gy = fy / (float)(Hf - 1) * 2.0f - 1.0f;
            gx = fminf(fmaxf(gx, -10.0f), 10.0f);
            gy = fminf(fmaxf(gy, -10.0f), 10.0f);
        }
        float px = (gx + 1.0f) * 0.5f * (float)(Wf - 1);
        float py = (gy + 1.0f) * 0.5f * (float)(Hf - 1);
        float x0f = floorf(px), y0f = floorf(py);
        int x0 = (int)x0f, y0 = (int)y0f;
        float wx1 = px - x0f, wy1 = py - y0f;
        float wx0 = 1.0f - wx1, wy0 = 1.0f - wy1;

        int   cx[4] = {x0, x0 + 1, x0, x0 + 1};
        int   cy[4] = {y0, y0, y0 + 1, y0 + 1};
        float cw[4] = {wx0 * wy0, wx1 * wy0, wx0 * wy1, wx1 * wy1};
#pragma unroll
        for (int k = 0; k < 4; k++) {
            int xi = cx[k], yi = cy[k];
            bool valid = (xi >= 0) && (xi < Wf) && (yi >= 0) && (yi < Hf);
            int xc = min(max(xi, 0), Wf - 1);
            int yc = min(max(yi, 0), Hf - 1);
            sidx[l * 4 + k] = yc * Wf + xc;
            sw[l * 4 + k]   = valid ? cw[k] : 0.0f;
        }
    }
    __syncthreads();

    const int c = tid;
    const float* base0 = f0 + (size_t)(bn * C_ + c) * 22400;
    const float* base1 = f1 + (size_t)(bn * C_ + c) * 5600;
    const float* base2 = f2 + (size_t)(bn * C_ + c) * 1400;
    const float* base3 = f3 + (size_t)(bn * C_ + c) * 350;
    const float* bases[4] = {base0, base1, base2, base3};

    float sum = 0.0f;
#pragma unroll
    for (int l = 0; l < 4; l++) {
#pragma unroll
        for (int k = 0; k < 4; k++) {
            float w = sw[l * 4 + k];
            if (w != 0.0f) sum += w * __ldg(&bases[l][sidx[l * 4 + k]]);
        }
    }
    float v = 0.25f * sum;
    __nv_bfloat16 hi, lo;
    split_bf16(v, hi, lo);
    const size_t off = (size_t)p * C_ + c;
    g_ms_hi[off] = hi;
    g_ms_lo[off] = lo;
}

// ---------------------------------------------------------------------------
// Tensor-core GEMM (bf16x3 decomposition, fp32 accumulate):
// out[m, j] = (sum_k A[m,k] * W[j,k] + bias[j]) * keep[m]
// Block 128(M) x 64(N), 8 warps, warp tile 32x32. grid (4, ceil(M/128)).
// ---------------------------------------------------------------------------
#define KSTR 24   // smem row stride in bf16 (48B: 16B-aligned, ldmatrix conflict-free)

__global__ __launch_bounds__(256) void mma_gemm(
    const __nv_bfloat16* __restrict__ Ahi, const __nv_bfloat16* __restrict__ Alo,
    const __nv_bfloat16* __restrict__ Bhi, const __nv_bfloat16* __restrict__ Blo,
    const float* __restrict__ bias, const float* __restrict__ keep,
    float* __restrict__ out, int M)
{
    __shared__ __align__(16) __nv_bfloat16 sA[2][2][128 * KSTR];
    __shared__ __align__(16) __nv_bfloat16 sB[2][2][64 * KSTR];

    const int tid  = threadIdx.x;
    const int lane = tid & 31, warp = tid >> 5;
    const int wm = warp & 3, wn = warp >> 2;
    const int row0 = blockIdx.y * 128, col0 = blockIdx.x * 64;

    const int ar = tid >> 1;                 // 0..127
    const int ak = (tid & 1) * 8;            // 0 / 8
    const int garow = min(row0 + ar, M - 1);
    const __nv_bfloat16* pAhi = Ahi + (size_t)garow * 256 + ak;
    const __nv_bfloat16* pAlo = Alo + (size_t)garow * 256 + ak;
    const int bsel = tid >> 7;               // 0: hi, 1: lo
    const int br = (tid & 127) >> 1;         // 0..63
    const int bk = (tid & 1) * 8;
    const __nv_bfloat16* pB = (bsel ? Blo : Bhi) + (size_t)(col0 + br) * 256 + bk;

    const int sa_off = ar * KSTR + ak;
    const int sb_off = br * KSTR + bk;

    float acc[2][4][4];
#pragma unroll
    for (int i = 0; i < 2; i++)
#pragma unroll
        for (int j = 0; j < 4; j++)
#pragma unroll
            for (int k = 0; k < 4; k++) acc[i][j][k] = 0.0f;

    uint4 ah = *(const uint4*)pAhi;
    uint4 al = *(const uint4*)pAlo;
    uint4 bb = *(const uint4*)pB;
    *(uint4*)&sA[0][0][sa_off] = ah;
    *(uint4*)&sA[0][1][sa_off] = al;
    *(uint4*)&sB[0][bsel][sb_off] = bb;
    __syncthreads();

    const int a_r = lane & 15;
    const int a_c = (lane >> 4) * 8;
    const int b_n = (lane & 7) + ((lane & 16) ? 8 : 0);
    const int b_k = (lane & 8) ? 8 : 0;

#pragma unroll 1
    for (int t = 0; t < 16; t++) {
        const int buf = t & 1;
        if (t < 15) {
            const int k0 = (t + 1) * 16;
            ah = *(const uint4*)(pAhi + k0);
            al = *(const uint4*)(pAlo + k0);
            bb = *(const uint4*)(pB + k0);
        }

        unsigned afh[2][4], afl[2][4], bfh[2][4], bfl[2][4];
#pragma unroll
        for (int mf = 0; mf < 2; mf++) {
            const int rbase = (wm * 32 + mf * 16 + a_r) * KSTR + a_c;
            ldsm4(afh[mf], (unsigned)__cvta_generic_to_shared(&sA[buf][0][rbase]));
            ldsm4(afl[mf], (unsigned)__cvta_generic_to_shared(&sA[buf][1][rbase]));
        }
#pragma unroll
        for (int nf2 = 0; nf2 < 2; nf2++) {
            const int nbase = (wn * 32 + nf2 * 16 + b_n) * KSTR + b_k;
            ldsm4(bfh[nf2], (unsigned)__cvta_generic_to_shared(&sB[buf][0][nbase]));
            ldsm4(bfl[nf2], (unsigned)__cvta_generic_to_shared(&sB[buf][1][nbase]));
        }
#pragma unroll
        for (int mf = 0; mf < 2; mf++)
#pragma unroll
            for (int nf = 0; nf < 4; nf++) {
                const int nf2 = nf >> 1, h = (nf & 1) * 2;
                mma16816(acc[mf][nf], afh[mf], &bfh[nf2][h]);   // hi*hi
                mma16816(acc[mf][nf], afh[mf], &bfl[nf2][h]);   // hi*lo
                mma16816(acc[mf][nf], afl[mf], &bfh[nf2][h]);   // lo*hi
            }

        if (t < 15) {
            const int nb = buf ^ 1;
            *(uint4*)&sA[nb][0][sa_off] = ah;
            *(uint4*)&sA[nb][1][sa_off] = al;
            *(uint4*)&sB[nb][bsel][sb_off] = bb;
        }
        __syncthreads();
    }

#pragma unroll
    for (int mf = 0; mf < 2; mf++)
#pragma unroll
        for (int nf = 0; nf < 4; nf++) {
            const int r  = row0 + wm * 32 + mf * 16 + (lane >> 2);
            const int cg = col0 + wn * 32 + nf * 8 + (lane & 3) * 2;
            const float b0v = bias[cg], b1v = bias[cg + 1];
            if (r < M) {
                const float ks = keep ? keep[r] : 1.0f;
                float2 o = make_float2((acc[mf][nf][0] + b0v) * ks,
                                       (acc[mf][nf][1] + b1v) * ks);
                *(float2*)(out + (size_t)r * 256 + cg) = o;
            }
            const int r2 = r + 8;
            if (r2 < M) {
                const float ks = keep ? keep[r2] : 1.0f;
                float2 o = make_float2((acc[mf][nf][2] + b0v) * ks,
                                       (acc[mf][nf][3] + b1v) * ks);
                *(float2*)(out + (size_t)r2 * 256 + cg) = o;
            }
        }
}

// ---------------------------------------------------------------------------
// SGEMM 64x64 (fp32 SIMT) — kept for the fully-overlapped q projection
// ---------------------------------------------------------------------------
__global__ __launch_bounds__(256) void sgemm64(const float* __restrict__ A,
                                               const float* __restrict__ W,
                                               const float* __restrict__ bias,
                                               const float* __restrict__ keep,
                                               float* __restrict__ out, int M)
{
    __shared__ float As[2][16][68];
    __shared__ float Bs[2][16][68];

    const int tid  = threadIdx.x;
    const int row0 = blockIdx.y * 64;
    const int col0 = blockIdx.x * 64;

    const int tx = tid & 15;
    const int ty = tid >> 4;
    const int lr = tid >> 2;
    const int lk = (tid & 3) * 4;

    const int gr = row0 + lr;
    const float* Aptr = A + (size_t)gr * 256 + lk;
    const float* Wptr = W + (size_t)(col0 + lr) * 256 + lk;

    float acc[4][4];
#pragma unroll
    for (int i = 0; i < 4; i++)
#pragma unroll
        for (int j = 0; j < 4; j++) acc[i][j] = 0.0f;

    float4 av = (gr < M) ? *(const float4*)(Aptr) : make_float4(0.f,0.f,0.f,0.f);
    float4 bv = *(const float4*)(Wptr);
    As[0][lk+0][lr]=av.x; As[0][lk+1][lr]=av.y; As[0][lk+2][lr]=av.z; As[0][lk+3][lr]=av.w;
    Bs[0][lk+0][lr]=bv.x; Bs[0][lk+1][lr]=bv.y; Bs[0][lk+2][lr]=bv.z; Bs[0][lk+3][lr]=bv.w;
    __syncthreads();

#pragma unroll 1
    for (int t = 0; t < 16; t++) {
        const int buf = t & 1;
        if (t < 15) {
            const int k0 = (t + 1) * 16;
            av = (gr < M) ? *(const float4*)(Aptr + k0) : make_float4(0.f,0.f,0.f,0.f);
            bv = *(const float4*)(Wptr + k0);
        }
#pragma unroll
        for (int kk = 0; kk < 16; kk++) {
            float a[4], b[4];
            *(float4*)a = *(const float4*)&As[buf][kk][ty * 4];
            *(float4*)b = *(const float4*)&Bs[buf][kk][tx * 4];
#pragma unroll
            for (int i = 0; i < 4; i++)
#pragma unroll
                for (int j = 0; j < 4; j++) acc[i][j] += a[i] * b[j];
        }
        if (t < 15) {
            const int nb = buf ^ 1;
            As[nb][lk+0][lr]=av.x; As[nb][lk+1][lr]=av.y; As[nb][lk+2][lr]=av.z; As[nb][lk+3][lr]=av.w;
            Bs[nb][lk+0][lr]=bv.x; Bs[nb][lk+1][lr]=bv.y; Bs[nb][lk+2][lr]=bv.z; Bs[nb][lk+3][lr]=bv.w;
        }
        __syncthreads();
    }

    const float4 bias4 = *(const float4*)(bias + col0 + tx * 4);
#pragma unroll
    for (int i = 0; i < 4; i++) {
        int r = row0 + ty * 4 + i;
        if (r >= M) continue;
        float ks = keep ? keep[r] : 1.0f;
        float4 o;
        o.x = (acc[i][0] + bias4.x) * ks;
        o.y = (acc[i][1] + bias4.y) * ks;
        o.z = (acc[i][2] + bias4.z) * ks;
        o.w = (acc[i][3] + bias4.w) * ks;
        *(float4*)(out + (size_t)r * 256 + col0 + tx * 4) = o;
    }
}

// ---------------------------------------------------------------------------
// Kernel: max over cameras + fused = relu(q + max) + q; emits bf16 hi/lo
// ---------------------------------------------------------------------------
__global__ void maxfuse_kernel()
{
    int idx = blockIdx.x * blockDim.x + threadIdx.x;   // over BQ * C/4
    if (idx >= BQ * (C_ / 4)) return;
    int m = idx / (C_ / 4);        // b*Q + q
    int c4 = idx % (C_ / 4);
    int b = m / Q_, qq = m % Q_;

    float4 mx = make_float4(-INFINITY, -INFINITY, -INFINITY, -INFINITY);
#pragma unroll
    for (int n = 0; n < NCAM; n++) {
        const float4 v = *(const float4*)&g_v[(((size_t)(b * NCAM + n) * Q_ + qq) * C_) + c4 * 4];
        mx.x = fmaxf(mx.x, v.x); mx.y = fmaxf(mx.y, v.y);
        mx.z = fmaxf(mx.z, v.z); mx.w = fmaxf(mx.w, v.w);
    }
    const float4 qv = *(const float4*)&g_q[(size_t)m * C_ + c4 * 4];
    float f[4];
    f[0] = fmaxf(qv.x + mx.x, 0.0f) + qv.x;
    f[1] = fmaxf(qv.y + mx.y, 0.0f) + qv.y;
    f[2] = fmaxf(qv.z + mx.z, 0.0f) + qv.z;
    f[3] = fmaxf(qv.w + mx.w, 0.0f) + qv.w;
    const size_t off = (size_t)m * C_ + c4 * 4;
#pragma unroll
    for (int i = 0; i < 4; i++) {
        __nv_bfloat16 hi, lo;
        split_bf16(f[i], hi, lo);
        g_fu_hi[off + i] = hi;
        g_fu_lo[off + i] = lo;
    }
}

// ---------------------------------------------------------------------------
// Launch. Side stream: weight splits + q-projection GEMM, overlapped with
// prep/sample/v-GEMM on the main stream.
// ---------------------------------------------------------------------------
extern "C" void kernel_launch(void* const* d_in, const int* in_sizes, int n_in,
                              void* d_out, int out_size)
{
    const float* query = (const float*)d_in[0];
    const float* refp  = (const float*)d_in[1];
    const void*  mask  = d_in[2];
    const float* intr  = (const float*)d_in[3];
    const float* ext   = (const float*)d_in[4];
    const float* f0    = (const float*)d_in[5];
    const float* f1    = (const float*)d_in[6];
    const float* f2    = (const float*)d_in[7];
    const float* f3    = (const float*)d_in[8];
    const float* Wq    = (const float*)d_in[9];
    const float* bq    = (const float*)d_in[10];
    const float* Wv    = (const float*)d_in[11];
    const float* bv    = (const float*)d_in[12];
    const float* Wo    = (const float*)d_in[13];
    const float* bo    = (const float*)d_in[14];
    float* out = (float*)d_out;

    float *p_q, *p_v, *p_keep;
    __nv_bfloat16 *p_ms_hi, *p_ms_lo, *p_fu_hi, *p_fu_lo;
    __nv_bfloat16 *p_wv_hi, *p_wv_lo, *p_wo_hi, *p_wo_lo;
    cudaGetSymbolAddress((void**)&p_q,     g_q);
    cudaGetSymbolAddress((void**)&p_v,     g_v);
    cudaGetSymbolAddress((void**)&p_keep,  g_keep);
    cudaGetSymbolAddress((void**)&p_ms_hi, g_ms_hi);
    cudaGetSymbolAddress((void**)&p_ms_lo, g_ms_lo);
    cudaGetSymbolAddress((void**)&p_fu_hi, g_fu_hi);
    cudaGetSymbolAddress((void**)&p_fu_lo, g_fu_lo);
    cudaGetSymbolAddress((void**)&p_wv_hi, g_wv_hi);
    cudaGetSymbolAddress((void**)&p_wv_lo, g_wv_lo);
    cudaGetSymbolAddress((void**)&p_wo_hi, g_wo_hi);
    cudaGetSymbolAddress((void**)&p_wo_lo, g_wo_lo);

    cudaStream_t s_side;
    cudaEvent_t ev_fork, ev_w, ev_join;
    cudaStreamCreateWithFlags(&s_side, cudaStreamNonBlocking);
    cudaEventCreateWithFlags(&ev_fork, cudaEventDisableTiming);
    cudaEventCreateWithFlags(&ev_w,    cudaEventDisableTiming);
    cudaEventCreateWithFlags(&ev_join, cudaEventDisableTiming);

    // side stream: weight splits, then q-proj
    cudaEventRecord(ev_fork, 0);
    cudaStreamWaitEvent(s_side, ev_fork, 0);
    wconv_kernel<<<256, 256, 0, s_side>>>(Wv, p_wv_hi, p_wv_lo);
    wconv_kernel<<<256, 256, 0, s_side>>>(Wo, p_wo_hi, p_wo_lo);
    cudaEventRecord(ev_w, s_side);
    sgemm64<<<dim3(4, (BQ + 63) / 64), 256, 0, s_side>>>(query, Wq, bq, nullptr, p_q, BQ);
    cudaEventRecord(ev_join, s_side);

    // main chain
    prep_kernel<<<1, 256>>>(mask, ext);
    sample_kernel<<<BNQ, 256>>>(refp, intr, f0, f1, f2, f3);

    // v = ms @ Wv^T + bv  (tensor cores, 340 blocks)
    cudaStreamWaitEvent(0, ev_w, 0);
    mma_gemm<<<dim3(4, (BNQ + 127) / 128), 256>>>(p_ms_hi, p_ms_lo, p_wv_hi, p_wv_lo,
                                                  bv, nullptr, p_v, BNQ);

    // join q, then fuse
    cudaStreamWaitEvent(0, ev_join, 0);
    maxfuse_kernel<<<(BQ * (C_ / 4) + 255) / 256, 256>>>();

    // out = (fused @ Wo^T + bo) * keep  (tensor cores, 60 blocks)
    mma_gemm<<<dim3(4, (BQ + 127) / 128), 256>>>(p_fu_hi, p_fu_lo, p_wo_hi, p_wo_lo,
                                                 bo, p_keep, out, BQ);
}

// round 15
// speedup vs baseline: 2.2673x; 1.0189x over previous
#include <cuda_runtime.h>
#include <cuda_bf16.h>
#include <math.h>

// ---------------------------------------------------------------------------
// Problem constants (fixed-shape instance)
// ---------------------------------------------------------------------------
#define B_    2
#define Q_    900
#define C_    256
#define NCAM  6
#define BQ    (B_ * Q_)          // 1800
#define BNQ   (B_ * NCAM * Q_)   // 10800

// ---------------------------------------------------------------------------
// Scratch (device globals; no dynamic allocation allowed)
// ---------------------------------------------------------------------------
__device__ float g_maskf[BQ];
__device__ float g_keep[BQ];
__device__ float g_invext[B_ * NCAM * 16];
__device__ __align__(16) __nv_bfloat16 g_ms_hi[BNQ * C_];   // 5.5 MB
__device__ __align__(16) __nv_bfloat16 g_ms_lo[BNQ * C_];
__device__ __align__(16) float g_q[BQ * C_];
__device__ __align__(16) float g_v[BNQ * C_];               // 11 MB
__device__ __align__(16) __nv_bfloat16 g_fu_hi[BQ * C_];
__device__ __align__(16) __nv_bfloat16 g_fu_lo[BQ * C_];
__device__ __align__(16) __nv_bfloat16 g_wv_hi[C_ * C_], g_wv_lo[C_ * C_];
__device__ __align__(16) __nv_bfloat16 g_wo_hi[C_ * C_], g_wo_lo[C_ * C_];

// ---------------------------------------------------------------------------
// MMA helpers (sm_80+ HMMA bf16, fp32 accumulate)
// ---------------------------------------------------------------------------
__device__ __forceinline__ void ldsm4(unsigned* r, unsigned addr) {
    asm volatile("ldmatrix.sync.aligned.m8n8.x4.shared.b16 {%0,%1,%2,%3}, [%4];"
        : "=r"(r[0]), "=r"(r[1]), "=r"(r[2]), "=r"(r[3]) : "r"(addr));
}
__device__ __forceinline__ void mma16816(float* c, const unsigned* a, const unsigned* b) {
    asm volatile(
        "mma.sync.aligned.m16n8k16.row.col.f32.bf16.bf16.f32 "
        "{%0,%1,%2,%3}, {%4,%5,%6,%7}, {%8,%9}, {%0,%1,%2,%3};"
        : "+f"(c[0]), "+f"(c[1]), "+f"(c[2]), "+f"(c[3])
        : "r"(a[0]), "r"(a[1]), "r"(a[2]), "r"(a[3]), "r"(b[0]), "r"(b[1]));
}
__device__ __forceinline__ void split_bf16(float v, __nv_bfloat16& hi, __nv_bfloat16& lo) {
    hi = __float2bfloat16(v);
    lo = __float2bfloat16(v - __bfloat162float(hi));
}

// 3x3 minor determinant of row-major 4x4 m, removing row r and column c
__device__ __forceinline__ double minor3(const double* m, int r, int c) {
    int rs[3], cs[3];
    int ri = 0, ci = 0;
#pragma unroll
    for (int k = 0; k < 4; k++) if (k != r) rs[ri++] = k;
#pragma unroll
    for (int k = 0; k < 4; k++) if (k != c) cs[ci++] = k;
    const double a = m[rs[0]*4+cs[0]], b = m[rs[0]*4+cs[1]], cc = m[rs[0]*4+cs[2]];
    const double d = m[rs[1]*4+cs[0]], e = m[rs[1]*4+cs[1]], f  = m[rs[1]*4+cs[2]];
    const double g = m[rs[2]*4+cs[0]], h = m[rs[2]*4+cs[1]], i2 = m[rs[2]*4+cs[2]];
    return a*(e*i2 - f*h) - b*(d*i2 - f*g) + cc*(d*h - e*g);
}

// ---------------------------------------------------------------------------
// Kernel 1: mask dtype detection + mask arrays + 4x4 extrinsic inverses
// One thread per (matrix, element): 192 threads across 6 warps; each thread
// computes one cofactor (inv[i][j] = (-1)^{i+j} M3(j,i) / det) + its own det.
// ---------------------------------------------------------------------------
__global__ void prep_kernel(const void* __restrict__ mask_raw,
                            const float* __restrict__ ext)
{
    __shared__ int s_byte;
    if (threadIdx.x == 0) s_byte = 0;
    __syncthreads();

    const unsigned int* w = (const unsigned int*)mask_raw;
    for (int i = threadIdx.x; i < 450; i += blockDim.x) {
        unsigned int x = w[i];
        if (x != 0u && x != 1u && x != 0x3F800000u) atomicOr(&s_byte, 1);
    }
    __syncthreads();
    const bool isbyte = (s_byte != 0);
    const unsigned char* bytes = (const unsigned char*)mask_raw;
    for (int i = threadIdx.x; i < BQ; i += blockDim.x) {
        bool mk = isbyte ? (bytes[i] != 0) : (w[i] != 0u);
        g_maskf[i] = mk ? 1.0f : 0.0f;
        g_keep[i]  = mk ? 0.0f : 1.0f;
    }

    const int t = threadIdx.x;
    if (t < B_ * NCAM * 16) {
        const int mat = t >> 4;
        const int e   = t & 15;
        const int i   = e >> 2;       // row of inverse
        const int j   = e & 3;        // col of inverse

        double m[16];
#pragma unroll
        for (int k = 0; k < 16; k++) m[k] = (double)ext[mat * 16 + k];

        const double sgn = ((i + j) & 1) ? -1.0 : 1.0;
        const double cof = sgn * minor3(m, j, i);

        const double det = m[0] * minor3(m, 0, 0) - m[1] * minor3(m, 0, 1)
                         + m[2] * minor3(m, 0, 2) - m[3] * minor3(m, 0, 3);

        float v = (float)(cof / det);
        if (isnan(v)) v = 0.0f;
        else if (isinf(v)) v = (v > 0.0f) ? 1e6f : -1e6f;
        g_invext[mat * 16 + i * 4 + j] = v;
    }
}

// ---------------------------------------------------------------------------
// Kernel: weight fp32 -> bf16 hi/lo split (65536 elements)
// ---------------------------------------------------------------------------
__global__ void wconv_kernel(const float* __restrict__ src,
                             __nv_bfloat16* __restrict__ hi,
                             __nv_bfloat16* __restrict__ lo)
{
    int i = blockIdx.x * 256 + threadIdx.x;
    float v = src[i];
    __nv_bfloat16 h, l;
    split_bf16(v, h, l);
    hi[i] = h; lo[i] = l;
}

// ---------------------------------------------------------------------------
// Kernel 2: projection + bilinear sampling (fused), emits bf16 hi/lo
// ---------------------------------------------------------------------------
__global__ void sample_kernel(const float* __restrict__ refp,
                              const float* __restrict__ intr,
                              const float* __restrict__ f0,
                              const float* __restrict__ f1,
                              const float* __restrict__ f2,
                              const float* __restrict__ f3)
{
    const int p  = blockIdx.x;       // (b*N+n)*Q + q
    const int bn = p / Q_;
    const int qq = p % Q_;
    const int b  = bn / NCAM;

    __shared__ int   sidx[16];
    __shared__ float sw[16];

    const int tid = threadIdx.x;
    if (tid < 4) {
        float rx, ry, rz;
        if (g_maskf[b * Q_ + qq] != 0.0f) {
            rx = ry = rz = -1000.0f;
        } else {
            const float* rp = refp + (b * Q_ + qq) * 3;
            rx = rp[0] * 102.4f - 51.2f;
            ry = rp[1] * 102.4f - 51.2f;
            rz = rp[2] * 102.4f - 51.2f;
        }
        const float* M = g_invext + bn * 16;
        float pch[4];
#pragma unroll
        for (int i = 0; i < 4; i++)
            pch[i] = M[i*4+0]*rx + M[i*4+1]*ry + M[i*4+2]*rz + M[i*4+3];

        float d = pch[2];
        if (isnan(d)) d = 10.0f;
        else if (isinf(d)) d = (d > 0.0f) ? 100.0f : -100.0f;
        const int invd = d < 1.5f;
        const float ds = fmaxf(d, 1.5f);
        const float pc0 = pch[0] / ds, pc1 = pch[1] / ds, pc2 = pch[2] / ds;

        const float* K = intr + bn * 9;
        float ix = K[0]*pc0 + K[1]*pc1 + K[2]*pc2;
        float iy = K[3]*pc0 + K[4]*pc1 + K[5]*pc2;
        ix = fminf(fmaxf(ix, -3000.0f), 3000.0f);
        iy = fminf(fmaxf(iy, -3000.0f), 3000.0f);

        const int l = tid;
        const int WFs[4] = {200, 100, 50, 25};
        const int HFs[4] = {112, 56, 28, 14};
        const float scl[4] = {0.25f, 0.125f, 0.0625f, 0.03125f};
        const int Wf = WFs[l], Hf = HFs[l];
        float gx, gy;
        if (invd) {
            gx = -100.0f; gy = -100.0f;
        } else {
            float fx = ix * scl[l];
            float fy = iy * scl[l];
            gx = fx / (float)(Wf - 1) * 2.0f - 1.0f;
            gy = fy / (float)(Hf - 1) * 2.0f - 1.0f;
            gx = fminf(fmaxf(gx, -10.0f), 10.0f);
            gy = fminf(fmaxf(gy, -10.0f), 10.0f);
        }
        float px = (gx + 1.0f) * 0.5f * (float)(Wf - 1);
        float py = (gy + 1.0f) * 0.5f * (float)(Hf - 1);
        float x0f = floorf(px), y0f = floorf(py);
        int x0 = (int)x0f, y0 = (int)y0f;
        float wx1 = px - x0f, wy1 = py - y0f;
        float wx0 = 1.0f - wx1, wy0 = 1.0f - wy1;

        int   cx[4] = {x0, x0 + 1, x0, x0 + 1};
        int   cy[4] = {y0, y0, y0 + 1, y0 + 1};
        float cw[4] = {wx0 * wy0, wx1 * wy0, wx0 * wy1, wx1 * wy1};
#pragma unroll
        for (int k = 0; k < 4; k++) {
            int xi = cx[k], yi = cy[k];
            bool valid = (xi >= 0) && (xi < Wf) && (yi >= 0) && (yi < Hf);
            int xc = min(max(xi, 0), Wf - 1);
            int yc = min(max(yi, 0), Hf - 1);
            sidx[l * 4 + k] = yc * Wf + xc;
            sw[l * 4 + k]   = valid ? cw[k] : 0.0f;
        }
    }
    __syncthreads();

    const int c = tid;
    const float* base0 = f0 + (size_t)(bn * C_ + c) * 22400;
    const float* base1 = f1 + (size_t)(bn * C_ + c) * 5600;
    const float* base2 = f2 + (size_t)(bn * C_ + c) * 1400;
    const float* base3 = f3 + (size_t)(bn * C_ + c) * 350;
    const float* bases[4] = {base0, base1, base2, base3};

    float sum = 0.0f;
#pragma unroll
    for (int l = 0; l < 4; l++) {
#pragma unroll
        for (int k = 0; k < 4; k++) {
            float w = sw[l * 4 + k];
            if (w != 0.0f) sum += w * __ldg(&bases[l][sidx[l * 4 + k]]);
        }
    }
    float v = 0.25f * sum;
    __nv_bfloat16 hi, lo;
    split_bf16(v, hi, lo);
    const size_t off = (size_t)p * C_ + c;
    g_ms_hi[off] = hi;
    g_ms_lo[off] = lo;
}

// ---------------------------------------------------------------------------
// Tensor-core GEMM (bf16x3 decomposition, fp32 accumulate):
// out[m, j] = (sum_k A[m,k] * W[j,k] + bias[j]) * keep[m]
// Block 128(M) x 64(N), 8 warps, warp tile 32x32. grid (4, ceil(M/128)).
// ---------------------------------------------------------------------------
#define KSTR 24   // smem row stride in bf16 (48B: 16B-aligned, ldmatrix conflict-free)

__global__ __launch_bounds__(256) void mma_gemm(
    const __nv_bfloat16* __restrict__ Ahi, const __nv_bfloat16* __restrict__ Alo,
    const __nv_bfloat16* __restrict__ Bhi, const __nv_bfloat16* __restrict__ Blo,
    const float* __restrict__ bias, const float* __restrict__ keep,
    float* __restrict__ out, int M)
{
    __shared__ __align__(16) __nv_bfloat16 sA[2][2][128 * KSTR];
    __shared__ __align__(16) __nv_bfloat16 sB[2][2][64 * KSTR];

    const int tid  = threadIdx.x;
    const int lane = tid & 31, warp = tid >> 5;
    const int wm = warp & 3, wn = warp >> 2;
    const int row0 = blockIdx.y * 128, col0 = blockIdx.x * 64;

    const int ar = tid >> 1;                 // 0..127
    const int ak = (tid & 1) * 8;            // 0 / 8
    const int garow = min(row0 + ar, M - 1);
    const __nv_bfloat16* pAhi = Ahi + (size_t)garow * 256 + ak;
    const __nv_bfloat16* pAlo = Alo + (size_t)garow * 256 + ak;
    const int bsel = tid >> 7;               // 0: hi, 1: lo
    const int br = (tid & 127) >> 1;         // 0..63
    const int bk = (tid & 1) * 8;
    const __nv_bfloat16* pB = (bsel ? Blo : Bhi) + (size_t)(col0 + br) * 256 + bk;

    const int sa_off = ar * KSTR + ak;
    const int sb_off = br * KSTR + bk;

    float acc[2][4][4];
#pragma unroll
    for (int i = 0; i < 2; i++)
#pragma unroll
        for (int j = 0; j < 4; j++)
#pragma unroll
            for (int k = 0; k < 4; k++) acc[i][j][k] = 0.0f;

    uint4 ah = *(const uint4*)pAhi;
    uint4 al = *(const uint4*)pAlo;
    uint4 bb = *(const uint4*)pB;
    *(uint4*)&sA[0][0][sa_off] = ah;
    *(uint4*)&sA[0][1][sa_off] = al;
    *(uint4*)&sB[0][bsel][sb_off] = bb;
    __syncthreads();

    const int a_r = lane & 15;
    const int a_c = (lane >> 4) * 8;
    const int b_n = (lane & 7) + ((lane & 16) ? 8 : 0);
    const int b_k = (lane & 8) ? 8 : 0;

#pragma unroll 1
    for (int t = 0; t < 16; t++) {
        const int buf = t & 1;
        if (t < 15) {
            const int k0 = (t + 1) * 16;
            ah = *(const uint4*)(pAhi + k0);
            al = *(const uint4*)(pAlo + k0);
            bb = *(const uint4*)(pB + k0);
        }

        unsigned afh[2][4], afl[2][4], bfh[2][4], bfl[2][4];
#pragma unroll
        for (int mf = 0; mf < 2; mf++) {
            const int rbase = (wm * 32 + mf * 16 + a_r) * KSTR + a_c;
            ldsm4(afh[mf], (unsigned)__cvta_generic_to_shared(&sA[buf][0][rbase]));
            ldsm4(afl[mf], (unsigned)__cvta_generic_to_shared(&sA[buf][1][rbase]));
        }
#pragma unroll
        for (int nf2 = 0; nf2 < 2; nf2++) {
            const int nbase = (wn * 32 + nf2 * 16 + b_n) * KSTR + b_k;
            ldsm4(bfh[nf2], (unsigned)__cvta_generic_to_shared(&sB[buf][0][nbase]));
            ldsm4(bfl[nf2], (unsigned)__cvta_generic_to_shared(&sB[buf][1][nbase]));
        }
#pragma unroll
        for (int mf = 0; mf < 2; mf++)
#pragma unroll
            for (int nf = 0; nf < 4; nf++) {
                const int nf2 = nf >> 1, h = (nf & 1) * 2;
                mma16816(acc[mf][nf], afh[mf], &bfh[nf2][h]);   // hi*hi
                mma16816(acc[mf][nf], afh[mf], &bfl[nf2][h]);   // hi*lo
                mma16816(acc[mf][nf], afl[mf], &bfh[nf2][h]);   // lo*hi
            }

        if (t < 15) {
            const int nb = buf ^ 1;
            *(uint4*)&sA[nb][0][sa_off] = ah;
            *(uint4*)&sA[nb][1][sa_off] = al;
            *(uint4*)&sB[nb][bsel][sb_off] = bb;
        }
        __syncthreads();
    }

#pragma unroll
    for (int mf = 0; mf < 2; mf++)
#pragma unroll
        for (int nf = 0; nf < 4; nf++) {
            const int r  = row0 + wm * 32 + mf * 16 + (lane >> 2);
            const int cg = col0 + wn * 32 + nf * 8 + (lane & 3) * 2;
            const float b0v = bias[cg], b1v = bias[cg + 1];
            if (r < M) {
                const float ks = keep ? keep[r] : 1.0f;
                float2 o = make_float2((acc[mf][nf][0] + b0v) * ks,
                                       (acc[mf][nf][1] + b1v) * ks);
                *(float2*)(out + (size_t)r * 256 + cg) = o;
            }
            const int r2 = r + 8;
            if (r2 < M) {
                const float ks = keep ? keep[r2] : 1.0f;
                float2 o = make_float2((acc[mf][nf][2] + b0v) * ks,
                                       (acc[mf][nf][3] + b1v) * ks);
                *(float2*)(out + (size_t)r2 * 256 + cg) = o;
            }
        }
}

// ---------------------------------------------------------------------------
// SGEMM 64x64 (fp32 SIMT) — kept for the fully-overlapped q projection
// ---------------------------------------------------------------------------
__global__ __launch_bounds__(256) void sgemm64(const float* __restrict__ A,
                                               const float* __restrict__ W,
                                               const float* __restrict__ bias,
                                               const float* __restrict__ keep,
                                               float* __restrict__ out, int M)
{
    __shared__ float As[2][16][68];
    __shared__ float Bs[2][16][68];

    const int tid  = threadIdx.x;
    const int row0 = blockIdx.y * 64;
    const int col0 = blockIdx.x * 64;

    const int tx = tid & 15;
    const int ty = tid >> 4;
    const int lr = tid >> 2;
    const int lk = (tid & 3) * 4;

    const int gr = row0 + lr;
    const float* Aptr = A + (size_t)gr * 256 + lk;
    const float* Wptr = W + (size_t)(col0 + lr) * 256 + lk;

    float acc[4][4];
#pragma unroll
    for (int i = 0; i < 4; i++)
#pragma unroll
        for (int j = 0; j < 4; j++) acc[i][j] = 0.0f;

    float4 av = (gr < M) ? *(const float4*)(Aptr) : make_float4(0.f,0.f,0.f,0.f);
    float4 bv = *(const float4*)(Wptr);
    As[0][lk+0][lr]=av.x; As[0][lk+1][lr]=av.y; As[0][lk+2][lr]=av.z; As[0][lk+3][lr]=av.w;
    Bs[0][lk+0][lr]=bv.x; Bs[0][lk+1][lr]=bv.y; Bs[0][lk+2][lr]=bv.z; Bs[0][lk+3][lr]=bv.w;
    __syncthreads();

#pragma unroll 1
    for (int t = 0; t < 16; t++) {
        const int buf = t & 1;
        if (t < 15) {
            const int k0 = (t + 1) * 16;
            av = (gr < M) ? *(const float4*)(Aptr + k0) : make_float4(0.f,0.f,0.f,0.f);
            bv = *(const float4*)(Wptr + k0);
        }
#pragma unroll
        for (int kk = 0; kk < 16; kk++) {
            float a[4], b[4];
            *(float4*)a = *(const float4*)&As[buf][kk][ty * 4];
            *(float4*)b = *(const float4*)&Bs[buf][kk][tx * 4];
#pragma unroll
            for (int i = 0; i < 4; i++)
#pragma unroll
                for (int j = 0; j < 4; j++) acc[i][j] += a[i] * b[j];
        }
        if (t < 15) {
            const int nb = buf ^ 1;
            As[nb][lk+0][lr]=av.x; As[nb][lk+1][lr]=av.y; As[nb][lk+2][lr]=av.z; As[nb][lk+3][lr]=av.w;
            Bs[nb][lk+0][lr]=bv.x; Bs[nb][lk+1][lr]=bv.y; Bs[nb][lk+2][lr]=bv.z; Bs[nb][lk+3][lr]=bv.w;
        }
        __syncthreads();
    }

    const float4 bias4 = *(const float4*)(bias + col0 + tx * 4);
#pragma unroll
    for (int i = 0; i < 4; i++) {
        int r = row0 + ty * 4 + i;
        if (r >= M) continue;
        float ks = keep ? keep[r] : 1.0f;
        float4 o;
        o.x = (acc[i][0] + bias4.x) * ks;
        o.y = (acc[i][1] + bias4.y) * ks;
        o.z = (acc[i][2] + bias4.z) * ks;
        o.w = (acc[i][3] + bias4.w) * ks;
        *(float4*)(out + (size_t)r * 256 + col0 + tx * 4) = o;
    }
}

// ---------------------------------------------------------------------------
// Kernel: max over cameras + fused = relu(q + max) + q; emits bf16 hi/lo
// ---------------------------------------------------------------------------
__global__ void maxfuse_kernel()
{
    int idx = blockIdx.x * blockDim.x + threadIdx.x;   // over BQ * C/4
    if (idx >= BQ * (C_ / 4)) return;
    int m = idx / (C_ / 4);        // b*Q + q
    int c4 = idx % (C_ / 4);
    int b = m / Q_, qq = m % Q_;

    float4 mx = make_float4(-INFINITY, -INFINITY, -INFINITY, -INFINITY);
#pragma unroll
    for (int n = 0; n < NCAM; n++) {
        const float4 v = *(const float4*)&g_v[(((size_t)(b * NCAM + n) * Q_ + qq) * C_) + c4 * 4];
        mx.x = fmaxf(mx.x, v.x); mx.y = fmaxf(mx.y, v.y);
        mx.z = fmaxf(mx.z, v.z); mx.w = fmaxf(mx.w, v.w);
    }
    const float4 qv = *(const float4*)&g_q[(size_t)m * C_ + c4 * 4];
    float f[4];
    f[0] = fmaxf(qv.x + mx.x, 0.0f) + qv.x;
    f[1] = fmaxf(qv.y + mx.y, 0.0f) + qv.y;
    f[2] = fmaxf(qv.z + mx.z, 0.0f) + qv.z;
    f[3] = fmaxf(qv.w + mx.w, 0.0f) + qv.w;
    const size_t off = (size_t)m * C_ + c4 * 4;
#pragma unroll
    for (int i = 0; i < 4; i++) {
        __nv_bfloat16 hi, lo;
        split_bf16(f[i], hi, lo);
        g_fu_hi[off + i] = hi;
        g_fu_lo[off + i] = lo;
    }
}

// ---------------------------------------------------------------------------
// Launch. Side stream: weight splits + q-projection GEMM, overlapped with
// prep/sample/v-GEMM on the main stream.
// ---------------------------------------------------------------------------
extern "C" void kernel_launch(void* const* d_in, const int* in_sizes, int n_in,
                              void* d_out, int out_size)
{
    const float* query = (const float*)d_in[0];
    const float* refp  = (const float*)d_in[1];
    const void*  mask  = d_in[2];
    const float* intr  = (const float*)d_in[3];
    const float* ext   = (const float*)d_in[4];
    const float* f0    = (const float*)d_in[5];
    const float* f1    = (const float*)d_in[6];
    const float* f2    = (const float*)d_in[7];
    const float* f3    = (const float*)d_in[8];
    const float* Wq    = (const float*)d_in[9];
    const float* bq    = (const float*)d_in[10];
    const float* Wv    = (const float*)d_in[11];
    const float* bv    = (const float*)d_in[12];
    const float* Wo    = (const float*)d_in[13];
    const float* bo    = (const float*)d_in[14];
    float* out = (float*)d_out;

    float *p_q, *p_v, *p_keep;
    __nv_bfloat16 *p_ms_hi, *p_ms_lo, *p_fu_hi, *p_fu_lo;
    __nv_bfloat16 *p_wv_hi, *p_wv_lo, *p_wo_hi, *p_wo_lo;
    cudaGetSymbolAddress((void**)&p_q,     g_q);
    cudaGetSymbolAddress((void**)&p_v,     g_v);
    cudaGetSymbolAddress((void**)&p_keep,  g_keep);
    cudaGetSymbolAddress((void**)&p_ms_hi, g_ms_hi);
    cudaGetSymbolAddress((void**)&p_ms_lo, g_ms_lo);
    cudaGetSymbolAddress((void**)&p_fu_hi, g_fu_hi);
    cudaGetSymbolAddress((void**)&p_fu_lo, g_fu_lo);
    cudaGetSymbolAddress((void**)&p_wv_hi, g_wv_hi);
    cudaGetSymbolAddress((void**)&p_wv_lo, g_wv_lo);
    cudaGetSymbolAddress((void**)&p_wo_hi, g_wo_hi);
    cudaGetSymbolAddress((void**)&p_wo_lo, g_wo_lo);

    cudaStream_t s_side;
    cudaEvent_t ev_fork, ev_w, ev_join;
    cudaStreamCreateWithFlags(&s_side, cudaStreamNonBlocking);
    cudaEventCreateWithFlags(&ev_fork, cudaEventDisableTiming);
    cudaEventCreateWithFlags(&ev_w,    cudaEventDisableTiming);
    cudaEventCreateWithFlags(&ev_join, cudaEventDisableTiming);

    // side stream: weight splits, then q-proj
    cudaEventRecord(ev_fork, 0);
    cudaStreamWaitEvent(s_side, ev_fork, 0);
    wconv_kernel<<<256, 256, 0, s_side>>>(Wv, p_wv_hi, p_wv_lo);
    wconv_kernel<<<256, 256, 0, s_side>>>(Wo, p_wo_hi, p_wo_lo);
    cudaEventRecord(ev_w, s_side);
    sgemm64<<<dim3(4, (BQ + 63) / 64), 256, 0, s_side>>>(query, Wq, bq, nullptr, p_q, BQ);
    cudaEventRecord(ev_join, s_side);

    // main chain
    prep_kernel<<<1, 256>>>(mask, ext);
    sample_kernel<<<BNQ, 256>>>(refp, intr, f0, f1, f2, f3);

    // v = ms @ Wv^T + bv  (tensor cores, 340 blocks)
    cudaStreamWaitEvent(0, ev_w, 0);
    mma_gemm<<<dim3(4, (BNQ + 127) / 128), 256>>>(p_ms_hi, p_ms_lo, p_wv_hi, p_wv_lo,
                                                  bv, nullptr, p_v, BNQ);

    // join q, then fuse
    cudaStreamWaitEvent(0, ev_join, 0);
    maxfuse_kernel<<<(BQ * (C_ / 4) + 255) / 256, 256>>>();

    // out = (fused @ Wo^T + bo) * keep  (tensor cores, 60 blocks)
    mma_gemm<<<dim3(4, (BQ + 127) / 128), 256>>>(p_fu_hi, p_fu_lo, p_wo_hi, p_wo_lo,
                                                 bo, p_keep, out, BQ);
}